// round 8
// baseline (speedup 1.0000x reference)
#include <cuda_runtime.h>
#include <cuda_bf16.h>
#include <cstdint>
#include <cstddef>

#define NN 32768
#define EE 524288
#define HH 128
#define GG 64
#define NG 512   // nodes per graph

// ---------------- device scratch (static, no allocations) ----------------
__device__ int      g_ei64;
__device__ int      g_cnt[NN];
__device__ int      g_off[NN + 1];
__device__ int      g_cur[NN];
__device__ int      g_bsum[128];
__device__ int      g_boff[128];
__device__ int      g_srcs[EE];
__device__ float    g_dinv[NN];
__device__ float4   g_hs[NN * 32];                 // fp32 messages; later reused for V
__device__ uint32_t g_h_hi[NN * 64];               // h split-bf16 (2 elems per uint32)
__device__ uint32_t g_h_lo[NN * 64];
__device__ uint32_t g_q_hi[NN * 64];
__device__ uint32_t g_q_lo[NN * 64];
__device__ uint32_t g_k_hi[NN * 64];
__device__ uint32_t g_k_lo[NN * 64];
__device__ float    g_scores[(size_t)GG * NG * NG]; // 64 MB scaled scores
__device__ float    g_rowm[GG * NG];
__device__ float    g_rowz[GG * NG];
__device__ float    g_w[GG * NG];

// ---------------- bf16 mma.sync helpers ----------------
#define MMA_BF16(D, a0, a1, a2, a3, b0, b1)                                   \
    asm volatile(                                                             \
        "mma.sync.aligned.m16n8k16.row.col.f32.bf16.bf16.f32 "                \
        "{%0,%1,%2,%3}, {%4,%5,%6,%7}, {%8,%9}, {%0,%1,%2,%3};"               \
        : "+f"((D)[0]), "+f"((D)[1]), "+f"((D)[2]), "+f"((D)[3])              \
        : "r"(a0), "r"(a1), "r"(a2), "r"(a3), "r"(b0), "r"(b1))

#define PADB 80   // 32 bf16 per row padded to 80 bytes (conflict-free fragment LDS)

__device__ __forceinline__ void cvt_pair(uint8_t* hi, uint8_t* lo,
                                         uint32_t off, float4 v) {
    __nv_bfloat16 hx = __float2bfloat16(v.x), hy = __float2bfloat16(v.y);
    __nv_bfloat16 hz = __float2bfloat16(v.z), hw = __float2bfloat16(v.w);
    __nv_bfloat162 h0 = __halves2bfloat162(hx, hy);
    __nv_bfloat162 h1 = __halves2bfloat162(hz, hw);
    *(uint2*)(hi + off) = make_uint2(*(uint32_t*)&h0, *(uint32_t*)&h1);
    __nv_bfloat162 l0 = __floats2bfloat162_rn(v.x - __bfloat162float(hx),
                                              v.y - __bfloat162float(hy));
    __nv_bfloat162 l1 = __floats2bfloat162_rn(v.z - __bfloat162float(hz),
                                              v.w - __bfloat162float(hw));
    *(uint2*)(lo + off) = make_uint2(*(uint32_t*)&l0, *(uint32_t*)&l1);
}

__device__ __forceinline__ uint32_t pack_hi(float a, float b) {
    __nv_bfloat162 h = __halves2bfloat162(__float2bfloat16(a), __float2bfloat16(b));
    return *(uint32_t*)&h;
}
__device__ __forceinline__ uint32_t pack_lo(float a, float b) {
    __nv_bfloat16 ha = __float2bfloat16(a), hb = __float2bfloat16(b);
    __nv_bfloat162 l = __floats2bfloat162_rn(a - __bfloat162float(ha),
                                             b - __bfloat162float(hb));
    return *(uint32_t*)&l;
}

// ---------------- edge index accessors ----------------
__device__ __forceinline__ int edge_src(const void* ei, int e) {
    int v = g_ei64 ? (int)((const long long*)ei)[e] : ((const int*)ei)[e];
    return v & (NN - 1);
}
__device__ __forceinline__ int edge_dst(const void* ei, int e) {
    int v = g_ei64 ? (int)((const long long*)ei)[EE + e] : ((const int*)ei)[EE + e];
    return v & (NN - 1);
}

// fused: zero histogram everywhere; block 0 additionally detects edge dtype
__global__ void __launch_bounds__(256) k_dtype_zero(const void* ei) {
    int i = blockIdx.x * 256 + threadIdx.x;
    g_cnt[i] = 0;
    if (blockIdx.x == 0) {
        __shared__ int s_ok;
        if (threadIdx.x == 0) s_ok = 1;
        __syncthreads();
        const long long* p = (const long long*)ei;
        int bad = 0;
#pragma unroll
        for (int k = 0; k < 4; k++) {
            long long v = p[threadIdx.x * 4 + k];
            if (v < 0 || v >= NN) bad = 1;
        }
        if (bad) atomicExch(&s_ok, 0);
        __syncthreads();
        if (threadIdx.x == 0) g_ei64 = s_ok;
    }
}

__global__ void k_hist(const void* __restrict__ ei) {
    int e = blockIdx.x * blockDim.x + threadIdx.x;
    if (e < EE) atomicAdd(&g_cnt[edge_dst(ei, e)], 1);
}
__global__ void __launch_bounds__(256) k_scan1() {
    __shared__ int sh[256];
    int t = threadIdx.x;
    int i = blockIdx.x * 256 + t;
    int c = g_cnt[i];
    sh[t] = c;
    __syncthreads();
#pragma unroll
    for (int o = 1; o < 256; o <<= 1) {
        int v = (t >= o) ? sh[t - o] : 0;
        __syncthreads();
        sh[t] += v;
        __syncthreads();
    }
    g_off[i] = sh[t] - c;
    if (t == 255) g_bsum[blockIdx.x] = sh[255];
}
__global__ void __launch_bounds__(128) k_scan2() {
    __shared__ int sh[128];
    int t = threadIdx.x;
    int c = g_bsum[t];
    sh[t] = c;
    __syncthreads();
#pragma unroll
    for (int o = 1; o < 128; o <<= 1) {
        int v = (t >= o) ? sh[t - o] : 0;
        __syncthreads();
        sh[t] += v;
        __syncthreads();
    }
    g_boff[t] = sh[t] - c;
}
__global__ void __launch_bounds__(256) k_scan3() {
    int i = blockIdx.x * 256 + threadIdx.x;
    int off = g_off[i] + g_boff[i >> 8];
    g_off[i] = off;
    g_cur[i] = off;
    g_dinv[i] = rsqrtf((float)g_cnt[i] + 1.0f);
    if (i == 0) g_off[NN] = EE;
}
__global__ void k_fill(const void* __restrict__ ei) {
    int e = blockIdx.x * blockDim.x + threadIdx.x;
    if (e >= EE) return;
    int s = edge_src(ei, e);
    int d = edge_dst(ei, e);
    int slot = atomicAdd(&g_cur[d], 1);
    g_srcs[slot] = s;
}

// ---- shared GEMM core pieces --------------------------------------------
// W chunk transposed into [n][k] split-bf16 smem (both gemm kernels)
__device__ __forceinline__ void load_W_chunk(uint8_t* sB_hi, uint8_t* sB_lo,
                                             const float4* W4, int kc, int tid) {
#pragma unroll
    for (int it = 0; it < 4; it++) {
        int idx = it * 256 + tid;
        int kr = idx >> 5, c4 = idx & 31;
        float4 v = W4[(kc * 32 + kr) * 32 + c4];
        float vv[4] = {v.x, v.y, v.z, v.w};
#pragma unroll
        for (int j = 0; j < 4; j++) {
            __nv_bfloat16 h = __float2bfloat16(vv[j]);
            __nv_bfloat16 l = __float2bfloat16(vv[j] - __bfloat162float(h));
            int n = c4 * 4 + j;
            *(__nv_bfloat16*)(sB_hi + n * PADB + kr * 2) = h;
            *(__nv_bfloat16*)(sB_lo + n * PADB + kr * 2) = l;
        }
    }
}

// the split-3 MMA sweep over one 32-K chunk
__device__ __forceinline__ void mma_chunk(float d[4][4][4],
                                          const uint8_t* sA_hi, const uint8_t* sA_lo,
                                          const uint8_t* sB_hi, const uint8_t* sB_lo,
                                          int wm, int wn, int gid, int tig) {
#pragma unroll
    for (int ks = 0; ks < 2; ks++) {
        uint32_t bh[4][2], bl[4][2];
#pragma unroll
        for (int nt = 0; nt < 4; nt++) {
            int n = wn * 32 + nt * 8 + gid;
            const uint8_t* pb = sB_hi + n * PADB + ks * 32 + tig * 4;
            bh[nt][0] = *(const uint32_t*)pb;
            bh[nt][1] = *(const uint32_t*)(pb + 16);
            const uint8_t* pl = sB_lo + n * PADB + ks * 32 + tig * 4;
            bl[nt][0] = *(const uint32_t*)pl;
            bl[nt][1] = *(const uint32_t*)(pl + 16);
        }
#pragma unroll
        for (int mt = 0; mt < 4; mt++) {
            int r = wm * 64 + mt * 16 + gid;
            const uint8_t* pa  = sA_hi + r * PADB + ks * 32 + tig * 4;
            const uint8_t* pa8 = pa + 8 * PADB;
            uint32_t ah0 = *(const uint32_t*)pa,        ah1 = *(const uint32_t*)pa8;
            uint32_t ah2 = *(const uint32_t*)(pa + 16), ah3 = *(const uint32_t*)(pa8 + 16);
            const uint8_t* qa  = sA_lo + r * PADB + ks * 32 + tig * 4;
            const uint8_t* qa8 = qa + 8 * PADB;
            uint32_t al0 = *(const uint32_t*)qa,        al1 = *(const uint32_t*)qa8;
            uint32_t al2 = *(const uint32_t*)(qa + 16), al3 = *(const uint32_t*)(qa8 + 16);
#pragma unroll
            for (int nt = 0; nt < 4; nt++) {
                MMA_BF16(d[mt][nt], ah0, ah1, ah2, ah3, bh[nt][0], bh[nt][1]);
                MMA_BF16(d[mt][nt], ah0, ah1, ah2, ah3, bl[nt][0], bl[nt][1]);
                MMA_BF16(d[mt][nt], al0, al1, al2, al3, bh[nt][0], bh[nt][1]);
            }
        }
    }
}

// epilogue: write fp32 to g_hs (dstMode 0) or split-bf16 to q/k (dstMode 1/2)
__device__ __forceinline__ void gemm_epilogue(float d[4][4][4], const float* bias,
                                              int dstMode, size_t m0,
                                              int wm, int wn, int gid, int tig) {
    float* C = (float*)g_hs;
    uint32_t* Hq = (dstMode == 1) ? g_q_hi : g_k_hi;
    uint32_t* Lq = (dstMode == 1) ? g_q_lo : g_k_lo;
#pragma unroll
    for (int mt = 0; mt < 4; mt++) {
        size_t row0 = m0 + wm * 64 + mt * 16 + gid;
        size_t row1 = row0 + 8;
#pragma unroll
        for (int nt = 0; nt < 4; nt++) {
            int col = wn * 32 + nt * 8 + tig * 2;
            float bx = 0.f, by = 0.f;
            if (bias) { bx = bias[col]; by = bias[col + 1]; }
            float v00 = d[mt][nt][0] + bx, v01 = d[mt][nt][1] + by;
            float v10 = d[mt][nt][2] + bx, v11 = d[mt][nt][3] + by;
            if (dstMode == 0) {
                *(float2*)(C + row0 * 128 + col) = make_float2(v00, v01);
                *(float2*)(C + row1 * 128 + col) = make_float2(v10, v11);
            } else {
                int ci = col >> 1;
                Hq[row0 * 64 + ci] = pack_hi(v00, v01);
                Lq[row0 * 64 + ci] = pack_lo(v00, v01);
                Hq[row1 * 64 + ci] = pack_hi(v10, v11);
                Lq[row1 * 64 + ci] = pack_lo(v10, v11);
            }
        }
    }
}

// ---------------- GEMM, fp32 A input (conv1 only): C = A @ W ----------------
__global__ void __launch_bounds__(256) k_tgemm_f32A(const float* __restrict__ Aext,
                                                    const float* __restrict__ W,
                                                    const float* __restrict__ bias,
                                                    int dstMode) {
    __shared__ __align__(16) uint8_t sA_hi[128 * PADB];
    __shared__ __align__(16) uint8_t sA_lo[128 * PADB];
    __shared__ __align__(16) uint8_t sB_hi[128 * PADB];
    __shared__ __align__(16) uint8_t sB_lo[128 * PADB];

    int tid = threadIdx.x, wid = tid >> 5, lane = tid & 31;
    int gid = lane >> 2, tig = lane & 3;
    int wm = wid >> 2, wn = wid & 3;
    size_t m0 = (size_t)blockIdx.x * 128;
    const float4* A4 = (const float4*)(Aext + m0 * 128);
    const float4* W4 = (const float4*)W;

    float d[4][4][4];
#pragma unroll
    for (int mt = 0; mt < 4; mt++)
#pragma unroll
        for (int nt = 0; nt < 4; nt++)
#pragma unroll
            for (int c = 0; c < 4; c++) d[mt][nt][c] = 0.f;

    for (int kc = 0; kc < 4; kc++) {
#pragma unroll
        for (int it = 0; it < 4; it++) {
            int idx = it * 256 + tid;
            int row = idx >> 3, k4 = idx & 7;
            cvt_pair(sA_hi, sA_lo, row * PADB + k4 * 8, A4[row * 32 + kc * 8 + k4]);
        }
        load_W_chunk(sB_hi, sB_lo, W4, kc, tid);
        __syncthreads();
        mma_chunk(d, sA_hi, sA_lo, sB_hi, sB_lo, wm, wn, gid, tig);
        __syncthreads();
    }
    gemm_epilogue(d, bias, dstMode, m0, wm, wn, gid, tig);
}

// ---------------- GEMM, split-bf16 A input (= g_h): C = h @ W ----------------
__global__ void __launch_bounds__(256) k_tgemm_bfA(const float* __restrict__ W,
                                                   const float* __restrict__ bias,
                                                   int dstMode) {
    __shared__ __align__(16) uint8_t sA_hi[128 * PADB];
    __shared__ __align__(16) uint8_t sA_lo[128 * PADB];
    __shared__ __align__(16) uint8_t sB_hi[128 * PADB];
    __shared__ __align__(16) uint8_t sB_lo[128 * PADB];

    int tid = threadIdx.x, wid = tid >> 5, lane = tid & 31;
    int gid = lane >> 2, tig = lane & 3;
    int wm = wid >> 2, wn = wid & 3;
    size_t m0 = (size_t)blockIdx.x * 128;
    const uint2* Ah2 = (const uint2*)g_h_hi;
    const uint2* Al2 = (const uint2*)g_h_lo;
    const float4* W4 = (const float4*)W;

    float d[4][4][4];
#pragma unroll
    for (int mt = 0; mt < 4; mt++)
#pragma unroll
        for (int nt = 0; nt < 4; nt++)
#pragma unroll
            for (int c = 0; c < 4; c++) d[mt][nt][c] = 0.f;

    for (int kc = 0; kc < 4; kc++) {
#pragma unroll
        for (int it = 0; it < 4; it++) {
            int idx = it * 256 + tid;
            int row = idx >> 3, k4 = idx & 7;
            size_t gi = (m0 + row) * 32 + kc * 8 + k4;
            *(uint2*)(sA_hi + row * PADB + k4 * 8) = Ah2[gi];
            *(uint2*)(sA_lo + row * PADB + k4 * 8) = Al2[gi];
        }
        load_W_chunk(sB_hi, sB_lo, W4, kc, tid);
        __syncthreads();
        mma_chunk(d, sA_hi, sA_lo, sB_hi, sB_lo, wm, wn, gid, tig);
        __syncthreads();
    }
    gemm_epilogue(d, bias, dstMode, m0, wm, wn, gid, tig);
}

// ---------------- scores: S-tile = Q @ K^T * SCALE (split-bf16 inputs) ----------------
#define SCALE 0.08838834764831845f

__global__ void __launch_bounds__(256) k_tscores() {
    __shared__ __align__(16) uint8_t sA_hi[128 * PADB];
    __shared__ __align__(16) uint8_t sA_lo[128 * PADB];
    __shared__ __align__(16) uint8_t sB_hi[128 * PADB];
    __shared__ __align__(16) uint8_t sB_lo[128 * PADB];

    int tid = threadIdx.x, wid = tid >> 5, lane = tid & 31;
    int gid = lane >> 2, tig = lane & 3;
    int wm = wid >> 2, wn = wid & 3;
    int g = blockIdx.z, ti = blockIdx.y, tj = blockIdx.x;

    size_t qrow = (size_t)(g * NG + ti * 128);
    size_t krow = (size_t)(g * NG + tj * 128);
    const uint2* Qh2 = (const uint2*)g_q_hi;
    const uint2* Ql2 = (const uint2*)g_q_lo;
    const uint2* Kh2 = (const uint2*)g_k_hi;
    const uint2* Kl2 = (const uint2*)g_k_lo;

    float d[4][4][4];
#pragma unroll
    for (int mt = 0; mt < 4; mt++)
#pragma unroll
        for (int nt = 0; nt < 4; nt++)
#pragma unroll
            for (int c = 0; c < 4; c++) d[mt][nt][c] = 0.f;

    for (int kc = 0; kc < 4; kc++) {
#pragma unroll
        for (int it = 0; it < 4; it++) {
            int idx = it * 256 + tid;
            int row = idx >> 3, k4 = idx & 7;
            uint32_t off = row * PADB + k4 * 8;
            size_t qi = (qrow + row) * 32 + kc * 8 + k4;
            size_t ki = (krow + row) * 32 + kc * 8 + k4;
            *(uint2*)(sA_hi + off) = Qh2[qi];
            *(uint2*)(sA_lo + off) = Ql2[qi];
            *(uint2*)(sB_hi + off) = Kh2[ki];
            *(uint2*)(sB_lo + off) = Kl2[ki];
        }
        __syncthreads();
        mma_chunk(d, sA_hi, sA_lo, sB_hi, sB_lo, wm, wn, gid, tig);
        __syncthreads();
    }

    float* Sg = g_scores + (size_t)g * NG * NG;
#pragma unroll
    for (int mt = 0; mt < 4; mt++) {
        int i0 = ti * 128 + wm * 64 + mt * 16 + gid;
        int i1 = i0 + 8;
#pragma unroll
        for (int nt = 0; nt < 4; nt++) {
            int col = tj * 128 + wn * 32 + nt * 8 + tig * 2;
            *(float2*)(Sg + (size_t)i0 * NG + col) =
                make_float2(d[mt][nt][0] * SCALE, d[mt][nt][1] * SCALE);
            *(float2*)(Sg + (size_t)i1 * NG + col) =
                make_float2(d[mt][nt][2] * SCALE, d[mt][nt][3] * SCALE);
        }
    }
}

// ---------------- aggregate: h = relu(dinv_i*(dinv_i*hs_i + sum dinv_s*hs_s) + b) ----------------
// writes h as split-bf16
__global__ void __launch_bounds__(256) k_aggregate(const float* __restrict__ b) {
    int t = blockIdx.x * blockDim.x + threadIdx.x;
    int i = t >> 5;
    if (i >= NN) return;
    int lane = t & 31;

    float di = g_dinv[i];
    float4 self = g_hs[(size_t)i * 32 + lane];
    float4 acc;
    acc.x = di * self.x; acc.y = di * self.y;
    acc.z = di * self.z; acc.w = di * self.w;

    int j = g_off[i];
    int end = g_off[i + 1];
    for (; j + 1 < end; j += 2) {
        int s0 = g_srcs[j], s1 = g_srcs[j + 1];
        float w0 = g_dinv[s0], w1 = g_dinv[s1];
        float4 v0 = g_hs[(size_t)s0 * 32 + lane];
        float4 v1 = g_hs[(size_t)s1 * 32 + lane];
        acc.x += w0 * v0.x + w1 * v1.x;
        acc.y += w0 * v0.y + w1 * v1.y;
        acc.z += w0 * v0.z + w1 * v1.z;
        acc.w += w0 * v0.w + w1 * v1.w;
    }
    if (j < end) {
        int s0 = g_srcs[j];
        float w0 = g_dinv[s0];
        float4 v0 = g_hs[(size_t)s0 * 32 + lane];
        acc.x += w0 * v0.x; acc.y += w0 * v0.y;
        acc.z += w0 * v0.z; acc.w += w0 * v0.w;
    }
    float4 bb = ((const float4*)b)[lane];
    float o0 = fmaxf(acc.x * di + bb.x, 0.f);
    float o1 = fmaxf(acc.y * di + bb.y, 0.f);
    float o2 = fmaxf(acc.z * di + bb.z, 0.f);
    float o3 = fmaxf(acc.w * di + bb.w, 0.f);
    size_t base = (size_t)i * 64 + lane * 2;
    g_h_hi[base]     = pack_hi(o0, o1);
    g_h_hi[base + 1] = pack_hi(o2, o3);
    g_h_lo[base]     = pack_lo(o0, o1);
    g_h_lo[base + 1] = pack_lo(o2, o3);
}

// ---------------- per-row softmax stats ----------------
__global__ void k_rowstats() {
    int gt = blockIdx.x * blockDim.x + threadIdx.x;
    int row = gt >> 5, lane = gt & 31;
    if (row >= GG * NG) return;
    const float* r = g_scores + (size_t)row * NG;
    float v[16];
    float m = -1e30f;
#pragma unroll
    for (int i = 0; i < 16; i++) { v[i] = r[lane + i * 32]; m = fmaxf(m, v[i]); }
#pragma unroll
    for (int o = 16; o > 0; o >>= 1) m = fmaxf(m, __shfl_xor_sync(0xffffffffu, m, o));
    float z = 0.f;
#pragma unroll
    for (int i = 0; i < 16; i++) z += __expf(v[i] - m);
#pragma unroll
    for (int o = 16; o > 0; o >>= 1) z += __shfl_xor_sync(0xffffffffu, z, o);
    if (lane == 0) { g_rowm[row] = m; g_rowz[row] = 1.0f / z; g_w[row] = 0.f; }
}

// ---------------- column weights ----------------
__global__ void __launch_bounds__(512) k_colsum() {
    __shared__ float sm_m[128];
    __shared__ float sm_zi[128];
    int g = blockIdx.x, it = blockIdx.y, j = threadIdx.x;
    if (j < 128) {
        sm_m[j]  = g_rowm[g * NG + it * 128 + j];
        sm_zi[j] = g_rowz[g * NG + it * 128 + j];
    }
    __syncthreads();
    const float* Sg = g_scores + (size_t)g * NG * NG + (size_t)it * 128 * NG;
    float w = 0.f;
#pragma unroll 4
    for (int i = 0; i < 128; i++)
        w += __expf(Sg[(size_t)i * NG + j] - sm_m[i]) * sm_zi[i];
    atomicAdd(&g_w[g * NG + j], w);
}

// ---------------- pooled + MLP head ----------------
__global__ void __launch_bounds__(128) k_pooled_head(const float* __restrict__ Wh1,
                                                     const float* __restrict__ bh1,
                                                     const float* __restrict__ Wh2,
                                                     const float* __restrict__ bh2,
                                                     float* __restrict__ out) {
    int g = blockIdx.x, d = threadIdx.x;
    __shared__ float ws[NG];
    __shared__ float pooled[HH];
    __shared__ float hid[64];
    for (int i = d; i < NG; i += 128) ws[i] = g_w[g * NG + i];
    __syncthreads();
    const float* vg = (const float*)g_hs + (size_t)g * NG * HH;
    float acc = 0.f;
    for (int j = 0; j < NG; j++) acc += ws[j] * vg[j * HH + d];
    pooled[d] = acc * (1.0f / (float)NG);
    __syncthreads();
    if (d < 64) {
        float h = bh1[d];
#pragma unroll 8
        for (int k = 0; k < HH; k++) h += pooled[k] * Wh1[k * 64 + d];
        hid[d] = fmaxf(h, 0.f);
    }
    __syncthreads();
    if (d == 0) {
        float o = bh2[0];
#pragma unroll 8
        for (int h = 0; h < 64; h++) o += hid[h] * Wh2[h];
        out[g] = o;
    }
}

// ---------------- launch ----------------
extern "C" void kernel_launch(void* const* d_in, const int* in_sizes, int n_in,
                              void* d_out, int out_size) {
    const float* x   = (const float*)d_in[0];
    const void*  ei  = d_in[1];
    const float* W1  = (const float*)d_in[3];
    const float* b1  = (const float*)d_in[4];
    const float* W2  = (const float*)d_in[5];
    const float* b2  = (const float*)d_in[6];
    const float* Wq  = (const float*)d_in[7];
    const float* bq  = (const float*)d_in[8];
    const float* Wk  = (const float*)d_in[9];
    const float* bk  = (const float*)d_in[10];
    const float* Wv  = (const float*)d_in[11];
    const float* bv  = (const float*)d_in[12];
    const float* Wh1 = (const float*)d_in[13];
    const float* bh1 = (const float*)d_in[14];
    const float* Wh2 = (const float*)d_in[15];
    const float* bh2 = (const float*)d_in[16];
    float* out = (float*)d_out;

    k_dtype_zero<<<NN / 256, 256>>>(ei);           // #1
    k_hist<<<EE / 256, 256>>>(ei);                 // #2
    k_scan1<<<NN / 256, 256>>>();                  // #3
    k_tgemm_f32A<<<NN / 128, 256>>>(x, W1, nullptr, 0);  // #4 (profiled slot)
    k_scan2<<<1, 128>>>();                         // #5
    k_scan3<<<NN / 256, 256>>>();                  // #6
    k_fill<<<EE / 256, 256>>>(ei);                 // #7

    k_aggregate<<<NN * 32 / 256, 256>>>(b1);       // conv1 aggregate -> h (bf16 split)
    k_tgemm_bfA<<<NN / 128, 256>>>(W2, nullptr, 0);
    k_aggregate<<<NN * 32 / 256, 256>>>(b2);

    k_tgemm_bfA<<<NN / 128, 256>>>(Wq, bq, 1);
    k_tgemm_bfA<<<NN / 128, 256>>>(Wk, bk, 2);
    k_tgemm_bfA<<<NN / 128, 256>>>(Wv, bv, 0);     // V -> g_hs fp32

    dim3 sg(NG / 128, NG / 128, GG);
    k_tscores<<<sg, 256>>>();
    k_rowstats<<<GG * NG * 32 / 256, 256>>>();
    dim3 cs(GG, NG / 128);
    k_colsum<<<cs, 512>>>();
    k_pooled_head<<<GG, HH>>>(Wh1, bh1, Wh2, bh2, out);
}

// round 9
// speedup vs baseline: 1.1197x; 1.1197x over previous
#include <cuda_runtime.h>
#include <cuda_bf16.h>
#include <cstdint>
#include <cstddef>

#define NN 32768
#define EE 524288
#define HH 128
#define GG 64
#define NG 512   // nodes per graph

// ---------------- device scratch (static, no allocations) ----------------
__device__ int      g_ei64;
__device__ int      g_cnt[NN];
__device__ int      g_off[NN + 1];
__device__ int      g_cur[NN];
__device__ int      g_bsum[128];
__device__ int      g_boff[128];
__device__ int      g_srcs[EE];
__device__ float    g_dinv[NN];
__device__ float4   g_hs[NN * 32];                 // fp32 messages; later reused for V
__device__ uint32_t g_h_hi[NN * 64];               // h split-bf16 (2 elems per uint32)
__device__ uint32_t g_h_lo[NN * 64];
__device__ uint32_t g_q_hi[NN * 64];
__device__ uint32_t g_q_lo[NN * 64];
__device__ uint32_t g_k_hi[NN * 64];
__device__ uint32_t g_k_lo[NN * 64];
__device__ float    g_scores[(size_t)GG * NG * NG]; // 64 MB scaled scores
__device__ float    g_rowm[GG * NG];
__device__ float    g_rowz[GG * NG];
__device__ float    g_w[GG * NG];

// ---------------- bf16 mma.sync + ldmatrix helpers ----------------
#define MMA_BF16(D, a0, a1, a2, a3, b0, b1)                                   \
    asm volatile(                                                             \
        "mma.sync.aligned.m16n8k16.row.col.f32.bf16.bf16.f32 "                \
        "{%0,%1,%2,%3}, {%4,%5,%6,%7}, {%8,%9}, {%0,%1,%2,%3};"               \
        : "+f"((D)[0]), "+f"((D)[1]), "+f"((D)[2]), "+f"((D)[3])              \
        : "r"(a0), "r"(a1), "r"(a2), "r"(a3), "r"(b0), "r"(b1))

#define LDSM4(r0, r1, r2, r3, addr)                                           \
    asm volatile("ldmatrix.sync.aligned.m8n8.x4.shared.b16 {%0,%1,%2,%3}, [%4];" \
                 : "=r"(r0), "=r"(r1), "=r"(r2), "=r"(r3) : "r"(addr))

#define LDSM2(r0, r1, addr)                                                   \
    asm volatile("ldmatrix.sync.aligned.m8n8.x2.shared.b16 {%0,%1}, [%2];"    \
                 : "=r"(r0), "=r"(r1) : "r"(addr))

#define PADB 80   // 32 bf16 per row padded to 80 bytes (16B-aligned rows, bank-spread)

__device__ __forceinline__ void cvt_pair(uint8_t* hi, uint8_t* lo,
                                         uint32_t off, float4 v) {
    __nv_bfloat16 hx = __float2bfloat16(v.x), hy = __float2bfloat16(v.y);
    __nv_bfloat16 hz = __float2bfloat16(v.z), hw = __float2bfloat16(v.w);
    __nv_bfloat162 h0 = __halves2bfloat162(hx, hy);
    __nv_bfloat162 h1 = __halves2bfloat162(hz, hw);
    *(uint2*)(hi + off) = make_uint2(*(uint32_t*)&h0, *(uint32_t*)&h1);
    __nv_bfloat162 l0 = __floats2bfloat162_rn(v.x - __bfloat162float(hx),
                                              v.y - __bfloat162float(hy));
    __nv_bfloat162 l1 = __floats2bfloat162_rn(v.z - __bfloat162float(hz),
                                              v.w - __bfloat162float(hw));
    *(uint2*)(lo + off) = make_uint2(*(uint32_t*)&l0, *(uint32_t*)&l1);
}

__device__ __forceinline__ uint32_t pack_hi(float a, float b) {
    __nv_bfloat162 h = __halves2bfloat162(__float2bfloat16(a), __float2bfloat16(b));
    return *(uint32_t*)&h;
}
__device__ __forceinline__ uint32_t pack_lo(float a, float b) {
    __nv_bfloat16 ha = __float2bfloat16(a), hb = __float2bfloat16(b);
    __nv_bfloat162 l = __floats2bfloat162_rn(a - __bfloat162float(ha),
                                             b - __bfloat162float(hb));
    return *(uint32_t*)&l;
}

// ---------------- edge index accessors ----------------
__device__ __forceinline__ int edge_src(const void* ei, int e) {
    int v = g_ei64 ? (int)((const long long*)ei)[e] : ((const int*)ei)[e];
    return v & (NN - 1);
}
__device__ __forceinline__ int edge_dst(const void* ei, int e) {
    int v = g_ei64 ? (int)((const long long*)ei)[EE + e] : ((const int*)ei)[EE + e];
    return v & (NN - 1);
}

__global__ void __launch_bounds__(256) k_dtype_zero(const void* ei) {
    int i = blockIdx.x * 256 + threadIdx.x;
    g_cnt[i] = 0;
    if (blockIdx.x == 0) {
        __shared__ int s_ok;
        if (threadIdx.x == 0) s_ok = 1;
        __syncthreads();
        const long long* p = (const long long*)ei;
        int bad = 0;
#pragma unroll
        for (int k = 0; k < 4; k++) {
            long long v = p[threadIdx.x * 4 + k];
            if (v < 0 || v >= NN) bad = 1;
        }
        if (bad) atomicExch(&s_ok, 0);
        __syncthreads();
        if (threadIdx.x == 0) g_ei64 = s_ok;
    }
}

__global__ void k_hist(const void* __restrict__ ei) {
    int e = blockIdx.x * blockDim.x + threadIdx.x;
    if (e < EE) atomicAdd(&g_cnt[edge_dst(ei, e)], 1);
}
__global__ void __launch_bounds__(256) k_scan1() {
    __shared__ int sh[256];
    int t = threadIdx.x;
    int i = blockIdx.x * 256 + t;
    int c = g_cnt[i];
    sh[t] = c;
    __syncthreads();
#pragma unroll
    for (int o = 1; o < 256; o <<= 1) {
        int v = (t >= o) ? sh[t - o] : 0;
        __syncthreads();
        sh[t] += v;
        __syncthreads();
    }
    g_off[i] = sh[t] - c;
    if (t == 255) g_bsum[blockIdx.x] = sh[255];
}
__global__ void __launch_bounds__(128) k_scan2() {
    __shared__ int sh[128];
    int t = threadIdx.x;
    int c = g_bsum[t];
    sh[t] = c;
    __syncthreads();
#pragma unroll
    for (int o = 1; o < 128; o <<= 1) {
        int v = (t >= o) ? sh[t - o] : 0;
        __syncthreads();
        sh[t] += v;
        __syncthreads();
    }
    g_boff[t] = sh[t] - c;
}
__global__ void __launch_bounds__(256) k_scan3() {
    int i = blockIdx.x * 256 + threadIdx.x;
    int off = g_off[i] + g_boff[i >> 8];
    g_off[i] = off;
    g_cur[i] = off;
    g_dinv[i] = rsqrtf((float)g_cnt[i] + 1.0f);
    if (i == 0) g_off[NN] = EE;
}
__global__ void k_fill(const void* __restrict__ ei) {
    int e = blockIdx.x * blockDim.x + threadIdx.x;
    if (e >= EE) return;
    int s = edge_src(ei, e);
    int d = edge_dst(ei, e);
    int slot = atomicAdd(&g_cur[d], 1);
    g_srcs[slot] = s;
}

// ---- shared GEMM core pieces --------------------------------------------
__device__ __forceinline__ void load_W_chunk(uint8_t* sB_hi, uint8_t* sB_lo,
                                             const float4* W4, int kc, int tid) {
#pragma unroll
    for (int it = 0; it < 4; it++) {
        int idx = it * 256 + tid;
        int kr = idx >> 5, c4 = idx & 31;
        float4 v = W4[(kc * 32 + kr) * 32 + c4];
        float vv[4] = {v.x, v.y, v.z, v.w};
#pragma unroll
        for (int j = 0; j < 4; j++) {
            __nv_bfloat16 h = __float2bfloat16(vv[j]);
            __nv_bfloat16 l = __float2bfloat16(vv[j] - __bfloat162float(h));
            int n = c4 * 4 + j;
            *(__nv_bfloat16*)(sB_hi + n * PADB + kr * 2) = h;
            *(__nv_bfloat16*)(sB_lo + n * PADB + kr * 2) = l;
        }
    }
}

// split-3 MMA sweep over one 32-K chunk, ldmatrix fragment loads
__device__ __forceinline__ void mma_chunk(float d[4][4][4],
                                          uint32_t aHi, uint32_t aLo,
                                          uint32_t bHi, uint32_t bLo,
                                          int wm, int wn, int lane) {
    uint32_t aOff = (uint32_t)((wm * 64 + (lane & 15)) * PADB + (lane >> 4) * 16);
    uint32_t bOff = (uint32_t)((wn * 32 + (lane & 7)) * PADB + ((lane >> 3) & 1) * 16);
#pragma unroll
    for (int ks = 0; ks < 2; ks++) {
        uint32_t bh[4][2], bl[4][2];
#pragma unroll
        for (int nt = 0; nt < 4; nt++) {
            LDSM2(bh[nt][0], bh[nt][1], bHi + bOff + nt * 8 * PADB + ks * 32);
            LDSM2(bl[nt][0], bl[nt][1], bLo + bOff + nt * 8 * PADB + ks * 32);
        }
#pragma unroll
        for (int mt = 0; mt < 4; mt++) {
            uint32_t ah0, ah1, ah2, ah3, al0, al1, al2, al3;
            LDSM4(ah0, ah1, ah2, ah3, aHi + aOff + mt * 16 * PADB + ks * 32);
            LDSM4(al0, al1, al2, al3, aLo + aOff + mt * 16 * PADB + ks * 32);
#pragma unroll
            for (int nt = 0; nt < 4; nt++) {
                MMA_BF16(d[mt][nt], ah0, ah1, ah2, ah3, bh[nt][0], bh[nt][1]);
                MMA_BF16(d[mt][nt], ah0, ah1, ah2, ah3, bl[nt][0], bl[nt][1]);
                MMA_BF16(d[mt][nt], al0, al1, al2, al3, bh[nt][0], bh[nt][1]);
            }
        }
    }
}

// epilogue: write fp32 to g_hs (dstMode 0) or split-bf16 to q/k (dstMode 1/2)
__device__ __forceinline__ void gemm_epilogue(float d[4][4][4], const float* bias,
                                              int dstMode, size_t m0,
                                              int wm, int wn, int gid, int tig) {
    float* C = (float*)g_hs;
    uint32_t* Hq = (dstMode == 1) ? g_q_hi : g_k_hi;
    uint32_t* Lq = (dstMode == 1) ? g_q_lo : g_k_lo;
#pragma unroll
    for (int mt = 0; mt < 4; mt++) {
        size_t row0 = m0 + wm * 64 + mt * 16 + gid;
        size_t row1 = row0 + 8;
#pragma unroll
        for (int nt = 0; nt < 4; nt++) {
            int col = wn * 32 + nt * 8 + tig * 2;
            float bx = 0.f, by = 0.f;
            if (bias) { bx = bias[col]; by = bias[col + 1]; }
            float v00 = d[mt][nt][0] + bx, v01 = d[mt][nt][1] + by;
            float v10 = d[mt][nt][2] + bx, v11 = d[mt][nt][3] + by;
            if (dstMode == 0) {
                *(float2*)(C + row0 * 128 + col) = make_float2(v00, v01);
                *(float2*)(C + row1 * 128 + col) = make_float2(v10, v11);
            } else {
                int ci = col >> 1;
                Hq[row0 * 64 + ci] = pack_hi(v00, v01);
                Lq[row0 * 64 + ci] = pack_lo(v00, v01);
                Hq[row1 * 64 + ci] = pack_hi(v10, v11);
                Lq[row1 * 64 + ci] = pack_lo(v10, v11);
            }
        }
    }
}

// ---------------- GEMM, fp32 A input (conv1 only): C = A @ W ----------------
__global__ void __launch_bounds__(256, 2) k_tgemm_f32A(const float* __restrict__ Aext,
                                                       const float* __restrict__ W,
                                                       const float* __restrict__ bias,
                                                       int dstMode) {
    __shared__ __align__(16) uint8_t sA_hi[128 * PADB];
    __shared__ __align__(16) uint8_t sA_lo[128 * PADB];
    __shared__ __align__(16) uint8_t sB_hi[128 * PADB];
    __shared__ __align__(16) uint8_t sB_lo[128 * PADB];

    int tid = threadIdx.x, wid = tid >> 5, lane = tid & 31;
    int gid = lane >> 2, tig = lane & 3;
    int wm = wid >> 2, wn = wid & 3;
    size_t m0 = (size_t)blockIdx.x * 128;
    const float4* A4 = (const float4*)(Aext + m0 * 128);
    const float4* W4 = (const float4*)W;
    uint32_t aHi = (uint32_t)__cvta_generic_to_shared(sA_hi);
    uint32_t aLo = (uint32_t)__cvta_generic_to_shared(sA_lo);
    uint32_t bHi = (uint32_t)__cvta_generic_to_shared(sB_hi);
    uint32_t bLo = (uint32_t)__cvta_generic_to_shared(sB_lo);

    float d[4][4][4];
#pragma unroll
    for (int mt = 0; mt < 4; mt++)
#pragma unroll
        for (int nt = 0; nt < 4; nt++)
#pragma unroll
            for (int c = 0; c < 4; c++) d[mt][nt][c] = 0.f;

    for (int kc = 0; kc < 4; kc++) {
#pragma unroll
        for (int it = 0; it < 4; it++) {
            int idx = it * 256 + tid;
            int row = idx >> 3, k4 = idx & 7;
            cvt_pair(sA_hi, sA_lo, row * PADB + k4 * 8, A4[row * 32 + kc * 8 + k4]);
        }
        load_W_chunk(sB_hi, sB_lo, W4, kc, tid);
        __syncthreads();
        mma_chunk(d, aHi, aLo, bHi, bLo, wm, wn, lane);
        __syncthreads();
    }
    gemm_epilogue(d, bias, dstMode, m0, wm, wn, gid, tig);
}

// ---------------- GEMM, split-bf16 A (= g_h): C = h @ W ----------------
// qkv != 0: fused Q/K/V launch, weight selected by blockIdx.y
__global__ void __launch_bounds__(256, 2) k_tgemm_bfA(const float* __restrict__ W0,
                                                      const float* __restrict__ bias0,
                                                      const float* __restrict__ W1p,
                                                      const float* __restrict__ bias1,
                                                      const float* __restrict__ W2p,
                                                      const float* __restrict__ bias2,
                                                      int qkv) {
    __shared__ __align__(16) uint8_t sA_hi[128 * PADB];
    __shared__ __align__(16) uint8_t sA_lo[128 * PADB];
    __shared__ __align__(16) uint8_t sB_hi[128 * PADB];
    __shared__ __align__(16) uint8_t sB_lo[128 * PADB];

    int tid = threadIdx.x, wid = tid >> 5, lane = tid & 31;
    int gid = lane >> 2, tig = lane & 3;
    int wm = wid >> 2, wn = wid & 3;
    size_t m0 = (size_t)blockIdx.x * 128;

    const float* W = W0;
    const float* bias = bias0;
    int dstMode = 0;
    if (qkv) {
        int y = blockIdx.y;
        W = (y == 0) ? W0 : (y == 1) ? W1p : W2p;
        bias = (y == 0) ? bias0 : (y == 1) ? bias1 : bias2;
        dstMode = (y == 0) ? 1 : (y == 1) ? 2 : 0;  // q, k, v(fp32)
    }

    const uint2* Ah2 = (const uint2*)g_h_hi;
    const uint2* Al2 = (const uint2*)g_h_lo;
    const float4* W4 = (const float4*)W;
    uint32_t aHi = (uint32_t)__cvta_generic_to_shared(sA_hi);
    uint32_t aLo = (uint32_t)__cvta_generic_to_shared(sA_lo);
    uint32_t bHi = (uint32_t)__cvta_generic_to_shared(sB_hi);
    uint32_t bLo = (uint32_t)__cvta_generic_to_shared(sB_lo);

    float d[4][4][4];
#pragma unroll
    for (int mt = 0; mt < 4; mt++)
#pragma unroll
        for (int nt = 0; nt < 4; nt++)
#pragma unroll
            for (int c = 0; c < 4; c++) d[mt][nt][c] = 0.f;

    for (int kc = 0; kc < 4; kc++) {
#pragma unroll
        for (int it = 0; it < 4; it++) {
            int idx = it * 256 + tid;
            int row = idx >> 3, k4 = idx & 7;
            size_t gi = (m0 + row) * 32 + kc * 8 + k4;
            *(uint2*)(sA_hi + row * PADB + k4 * 8) = Ah2[gi];
            *(uint2*)(sA_lo + row * PADB + k4 * 8) = Al2[gi];
        }
        load_W_chunk(sB_hi, sB_lo, W4, kc, tid);
        __syncthreads();
        mma_chunk(d, aHi, aLo, bHi, bLo, wm, wn, lane);
        __syncthreads();
    }
    gemm_epilogue(d, bias, dstMode, m0, wm, wn, gid, tig);
}

// ---------------- scores: S-tile = Q @ K^T * SCALE ----------------
#define SCALE 0.08838834764831845f

__global__ void __launch_bounds__(256, 2) k_tscores() {
    __shared__ __align__(16) uint8_t sA_hi[128 * PADB];
    __shared__ __align__(16) uint8_t sA_lo[128 * PADB];
    __shared__ __align__(16) uint8_t sB_hi[128 * PADB];
    __shared__ __align__(16) uint8_t sB_lo[128 * PADB];

    int tid = threadIdx.x, wid = tid >> 5, lane = tid & 31;
    int gid = lane >> 2, tig = lane & 3;
    int wm = wid >> 2, wn = wid & 3;
    int g = blockIdx.z, ti = blockIdx.y, tj = blockIdx.x;

    size_t qrow = (size_t)(g * NG + ti * 128);
    size_t krow = (size_t)(g * NG + tj * 128);
    const uint2* Qh2 = (const uint2*)g_q_hi;
    const uint2* Ql2 = (const uint2*)g_q_lo;
    const uint2* Kh2 = (const uint2*)g_k_hi;
    const uint2* Kl2 = (const uint2*)g_k_lo;
    uint32_t aHi = (uint32_t)__cvta_generic_to_shared(sA_hi);
    uint32_t aLo = (uint32_t)__cvta_generic_to_shared(sA_lo);
    uint32_t bHi = (uint32_t)__cvta_generic_to_shared(sB_hi);
    uint32_t bLo = (uint32_t)__cvta_generic_to_shared(sB_lo);

    float d[4][4][4];
#pragma unroll
    for (int mt = 0; mt < 4; mt++)
#pragma unroll
        for (int nt = 0; nt < 4; nt++)
#pragma unroll
            for (int c = 0; c < 4; c++) d[mt][nt][c] = 0.f;

    for (int kc = 0; kc < 4; kc++) {
#pragma unroll
        for (int it = 0; it < 4; it++) {
            int idx = it * 256 + tid;
            int row = idx >> 3, k4 = idx & 7;
            uint32_t off = row * PADB + k4 * 8;
            size_t qi = (qrow + row) * 32 + kc * 8 + k4;
            size_t ki = (krow + row) * 32 + kc * 8 + k4;
            *(uint2*)(sA_hi + off) = Qh2[qi];
            *(uint2*)(sA_lo + off) = Ql2[qi];
            *(uint2*)(sB_hi + off) = Kh2[ki];
            *(uint2*)(sB_lo + off) = Kl2[ki];
        }
        __syncthreads();
        mma_chunk(d, aHi, aLo, bHi, bLo, wm, wn, lane);
        __syncthreads();
    }

    float* Sg = g_scores + (size_t)g * NG * NG;
#pragma unroll
    for (int mt = 0; mt < 4; mt++) {
        int i0 = ti * 128 + wm * 64 + mt * 16 + gid;
        int i1 = i0 + 8;
#pragma unroll
        for (int nt = 0; nt < 4; nt++) {
            int col = tj * 128 + wn * 32 + nt * 8 + tig * 2;
            *(float2*)(Sg + (size_t)i0 * NG + col) =
                make_float2(d[mt][nt][0] * SCALE, d[mt][nt][1] * SCALE);
            *(float2*)(Sg + (size_t)i1 * NG + col) =
                make_float2(d[mt][nt][2] * SCALE, d[mt][nt][3] * SCALE);
        }
    }
}

// ---------------- aggregate (writes h as split-bf16) ----------------
__global__ void __launch_bounds__(256) k_aggregate(const float* __restrict__ b) {
    int t = blockIdx.x * blockDim.x + threadIdx.x;
    int i = t >> 5;
    if (i >= NN) return;
    int lane = t & 31;

    float di = g_dinv[i];
    float4 self = g_hs[(size_t)i * 32 + lane];
    float4 acc;
    acc.x = di * self.x; acc.y = di * self.y;
    acc.z = di * self.z; acc.w = di * self.w;

    int j = g_off[i];
    int end = g_off[i + 1];
    for (; j + 1 < end; j += 2) {
        int s0 = g_srcs[j], s1 = g_srcs[j + 1];
        float w0 = g_dinv[s0], w1 = g_dinv[s1];
        float4 v0 = g_hs[(size_t)s0 * 32 + lane];
        float4 v1 = g_hs[(size_t)s1 * 32 + lane];
        acc.x += w0 * v0.x + w1 * v1.x;
        acc.y += w0 * v0.y + w1 * v1.y;
        acc.z += w0 * v0.z + w1 * v1.z;
        acc.w += w0 * v0.w + w1 * v1.w;
    }
    if (j < end) {
        int s0 = g_srcs[j];
        float w0 = g_dinv[s0];
        float4 v0 = g_hs[(size_t)s0 * 32 + lane];
        acc.x += w0 * v0.x; acc.y += w0 * v0.y;
        acc.z += w0 * v0.z; acc.w += w0 * v0.w;
    }
    float4 bb = ((const float4*)b)[lane];
    float o0 = fmaxf(acc.x * di + bb.x, 0.f);
    float o1 = fmaxf(acc.y * di + bb.y, 0.f);
    float o2 = fmaxf(acc.z * di + bb.z, 0.f);
    float o3 = fmaxf(acc.w * di + bb.w, 0.f);
    size_t base = (size_t)i * 64 + lane * 2;
    g_h_hi[base]     = pack_hi(o0, o1);
    g_h_hi[base + 1] = pack_hi(o2, o3);
    g_h_lo[base]     = pack_lo(o0, o1);
    g_h_lo[base + 1] = pack_lo(o2, o3);
}

// ---------------- per-row softmax stats ----------------
__global__ void k_rowstats() {
    int gt = blockIdx.x * blockDim.x + threadIdx.x;
    int row = gt >> 5, lane = gt & 31;
    if (row >= GG * NG) return;
    const float* r = g_scores + (size_t)row * NG;
    float v[16];
    float m = -1e30f;
#pragma unroll
    for (int i = 0; i < 16; i++) { v[i] = r[lane + i * 32]; m = fmaxf(m, v[i]); }
#pragma unroll
    for (int o = 16; o > 0; o >>= 1) m = fmaxf(m, __shfl_xor_sync(0xffffffffu, m, o));
    float z = 0.f;
#pragma unroll
    for (int i = 0; i < 16; i++) z += __expf(v[i] - m);
#pragma unroll
    for (int o = 16; o > 0; o >>= 1) z += __shfl_xor_sync(0xffffffffu, z, o);
    if (lane == 0) { g_rowm[row] = m; g_rowz[row] = 1.0f / z; g_w[row] = 0.f; }
}

// ---------------- column weights ----------------
__global__ void __launch_bounds__(512) k_colsum() {
    __shared__ float sm_m[128];
    __shared__ float sm_zi[128];
    int g = blockIdx.x, it = blockIdx.y, j = threadIdx.x;
    if (j < 128) {
        sm_m[j]  = g_rowm[g * NG + it * 128 + j];
        sm_zi[j] = g_rowz[g * NG + it * 128 + j];
    }
    __syncthreads();
    const float* Sg = g_scores + (size_t)g * NG * NG + (size_t)it * 128 * NG;
    float w = 0.f;
#pragma unroll 4
    for (int i = 0; i < 128; i++)
        w += __expf(Sg[(size_t)i * NG + j] - sm_m[i]) * sm_zi[i];
    atomicAdd(&g_w[g * NG + j], w);
}

// ---------------- pooled + MLP head ----------------
__global__ void __launch_bounds__(128) k_pooled_head(const float* __restrict__ Wh1,
                                                     const float* __restrict__ bh1,
                                                     const float* __restrict__ Wh2,
                                                     const float* __restrict__ bh2,
                                                     float* __restrict__ out) {
    int g = blockIdx.x, d = threadIdx.x;
    __shared__ float ws[NG];
    __shared__ float pooled[HH];
    __shared__ float hid[64];
    for (int i = d; i < NG; i += 128) ws[i] = g_w[g * NG + i];
    __syncthreads();
    const float* vg = (const float*)g_hs + (size_t)g * NG * HH;
    float acc = 0.f;
    for (int j = 0; j < NG; j++) acc += ws[j] * vg[j * HH + d];
    pooled[d] = acc * (1.0f / (float)NG);
    __syncthreads();
    if (d < 64) {
        float h = bh1[d];
#pragma unroll 8
        for (int k = 0; k < HH; k++) h += pooled[k] * Wh1[k * 64 + d];
        hid[d] = fmaxf(h, 0.f);
    }
    __syncthreads();
    if (d == 0) {
        float o = bh2[0];
#pragma unroll 8
        for (int h = 0; h < 64; h++) o += hid[h] * Wh2[h];
        out[g] = o;
    }
}

// ---------------- launch ----------------
extern "C" void kernel_launch(void* const* d_in, const int* in_sizes, int n_in,
                              void* d_out, int out_size) {
    const float* x   = (const float*)d_in[0];
    const void*  ei  = d_in[1];
    const float* W1  = (const float*)d_in[3];
    const float* b1  = (const float*)d_in[4];
    const float* W2  = (const float*)d_in[5];
    const float* b2  = (const float*)d_in[6];
    const float* Wq  = (const float*)d_in[7];
    const float* bq  = (const float*)d_in[8];
    const float* Wk  = (const float*)d_in[9];
    const float* bk  = (const float*)d_in[10];
    const float* Wv  = (const float*)d_in[11];
    const float* bv  = (const float*)d_in[12];
    const float* Wh1 = (const float*)d_in[13];
    const float* bh1 = (const float*)d_in[14];
    const float* Wh2 = (const float*)d_in[15];
    const float* bh2 = (const float*)d_in[16];
    float* out = (float*)d_out;

    k_dtype_zero<<<NN / 256, 256>>>(ei);           // #1
    k_hist<<<EE / 256, 256>>>(ei);                 // #2
    k_scan1<<<NN / 256, 256>>>();                  // #3
    k_tgemm_f32A<<<NN / 128, 256>>>(x, W1, nullptr, 0);  // #4 (profiled slot)
    k_scan2<<<1, 128>>>();                         // #5
    k_scan3<<<NN / 256, 256>>>();                  // #6
    k_fill<<<EE / 256, 256>>>(ei);                 // #7

    k_aggregate<<<NN * 32 / 256, 256>>>(b1);
    k_tgemm_bfA<<<NN / 128, 256>>>(W2, nullptr, nullptr, nullptr, nullptr, nullptr, 0);
    k_aggregate<<<NN * 32 / 256, 256>>>(b2);

    // fused Q/K/V: grid (256, 3)
    dim3 qkv(NN / 128, 3);
    k_tgemm_bfA<<<qkv, 256>>>(Wq, bq, Wk, bk, Wv, bv, 1);

    dim3 sg(NG / 128, NG / 128, GG);
    k_tscores<<<sg, 256>>>();
    k_rowstats<<<GG * NG * 32 / 256, 256>>>();
    dim3 cs(GG, NG / 128);
    k_colsum<<<cs, 512>>>();
    k_pooled_head<<<GG, HH>>>(Wh1, bh1, Wh2, bh2, out);
}

// round 10
// speedup vs baseline: 1.4573x; 1.3015x over previous
#include <cuda_runtime.h>
#include <cuda_bf16.h>
#include <cstdint>
#include <cstddef>

#define NN 32768
#define EE 524288
#define HH 128
#define GG 64
#define NG 512   // nodes per graph

// ---------------- device scratch (static, no allocations) ----------------
__device__ int      g_ei64;
__device__ int      g_cnt[NN];
__device__ int      g_off[NN + 1];
__device__ int      g_cur[NN];
__device__ int      g_bsum[128];
__device__ int      g_boff[128];
__device__ int      g_srcs[EE];
__device__ float    g_dinv[NN];
__device__ float4   g_hs[NN * 32];                 // fp32 messages; later reused for V
__device__ uint32_t g_h_hi[NN * 64];               // h split-bf16 (2 elems per uint32)
__device__ uint32_t g_h_lo[NN * 64];
__device__ uint32_t g_q_hi[NN * 64];               // also holds split x before QKV
__device__ uint32_t g_q_lo[NN * 64];
__device__ uint32_t g_k_hi[NN * 64];
__device__ uint32_t g_k_lo[NN * 64];
__device__ uint32_t g_wt_hi[5 * 128 * 64];         // 5 weights, transposed [n][k] split-bf16
__device__ uint32_t g_wt_lo[5 * 128 * 64];
__device__ float    g_scores[(size_t)GG * NG * NG]; // 64 MB scaled scores
__device__ float    g_rowm[GG * NG];
__device__ float    g_rowz[GG * NG];
__device__ float    g_w[GG * NG];

// ---------------- mma.sync / ldmatrix / cp.async helpers ----------------
#define MMA_BF16(D, a0, a1, a2, a3, b0, b1)                                   \
    asm volatile(                                                             \
        "mma.sync.aligned.m16n8k16.row.col.f32.bf16.bf16.f32 "                \
        "{%0,%1,%2,%3}, {%4,%5,%6,%7}, {%8,%9}, {%0,%1,%2,%3};"               \
        : "+f"((D)[0]), "+f"((D)[1]), "+f"((D)[2]), "+f"((D)[3])              \
        : "r"(a0), "r"(a1), "r"(a2), "r"(a3), "r"(b0), "r"(b1))

#define LDSM4(r0, r1, r2, r3, addr)                                           \
    asm volatile("ldmatrix.sync.aligned.m8n8.x4.shared.b16 {%0,%1,%2,%3}, [%4];" \
                 : "=r"(r0), "=r"(r1), "=r"(r2), "=r"(r3) : "r"(addr))

#define LDSM2(r0, r1, addr)                                                   \
    asm volatile("ldmatrix.sync.aligned.m8n8.x2.shared.b16 {%0,%1}, [%2];"    \
                 : "=r"(r0), "=r"(r1) : "r"(addr))

__device__ __forceinline__ void cp16(uint32_t dst, const void* src) {
    asm volatile("cp.async.ca.shared.global [%0], [%1], 16;" :: "r"(dst), "l"(src));
}
#define CP_COMMIT() asm volatile("cp.async.commit_group;" ::: "memory")
#define CP_WAIT(n)  asm volatile("cp.async.wait_group %0;" :: "n"(n) : "memory")

#define PADB 80            // 32 bf16 per row padded to 80 B (bank-disjoint ldmatrix)
#define TILE_B (128 * PADB)     // 10240 B per tile
#define STAGE_B (4 * TILE_B)    // 40960 B per pipeline stage
#define DSMEM (2 * STAGE_B)     // 81920 B dynamic smem

__device__ __forceinline__ uint32_t pack_hi(float a, float b) {
    __nv_bfloat162 h = __halves2bfloat162(__float2bfloat16(a), __float2bfloat16(b));
    return *(uint32_t*)&h;
}
__device__ __forceinline__ uint32_t pack_lo(float a, float b) {
    __nv_bfloat16 ha = __float2bfloat16(a), hb = __float2bfloat16(b);
    __nv_bfloat162 l = __floats2bfloat162_rn(a - __bfloat162float(ha),
                                             b - __bfloat162float(hb));
    return *(uint32_t*)&l;
}

// ---------------- edge index accessors ----------------
__device__ __forceinline__ int edge_src(const void* ei, int e) {
    int v = g_ei64 ? (int)((const long long*)ei)[e] : ((const int*)ei)[e];
    return v & (NN - 1);
}
__device__ __forceinline__ int edge_dst(const void* ei, int e) {
    int v = g_ei64 ? (int)((const long long*)ei)[EE + e] : ((const int*)ei)[EE + e];
    return v & (NN - 1);
}

__global__ void __launch_bounds__(256) k_dtype_zero(const void* ei) {
    int i = blockIdx.x * 256 + threadIdx.x;
    g_cnt[i] = 0;
    if (blockIdx.x == 0) {
        __shared__ int s_ok;
        if (threadIdx.x == 0) s_ok = 1;
        __syncthreads();
        const long long* p = (const long long*)ei;
        int bad = 0;
#pragma unroll
        for (int k = 0; k < 4; k++) {
            long long v = p[threadIdx.x * 4 + k];
            if (v < 0 || v >= NN) bad = 1;
        }
        if (bad) atomicExch(&s_ok, 0);
        __syncthreads();
        if (threadIdx.x == 0) g_ei64 = s_ok;
    }
}

__global__ void k_hist(const void* __restrict__ ei) {
    int e = blockIdx.x * blockDim.x + threadIdx.x;
    if (e < EE) atomicAdd(&g_cnt[edge_dst(ei, e)], 1);
}
__global__ void __launch_bounds__(256) k_scan1() {
    __shared__ int sh[256];
    int t = threadIdx.x;
    int i = blockIdx.x * 256 + t;
    int c = g_cnt[i];
    sh[t] = c;
    __syncthreads();
#pragma unroll
    for (int o = 1; o < 256; o <<= 1) {
        int v = (t >= o) ? sh[t - o] : 0;
        __syncthreads();
        sh[t] += v;
        __syncthreads();
    }
    g_off[i] = sh[t] - c;
    if (t == 255) g_bsum[blockIdx.x] = sh[255];
}
__global__ void __launch_bounds__(128) k_scan2() {
    __shared__ int sh[128];
    int t = threadIdx.x;
    int c = g_bsum[t];
    sh[t] = c;
    __syncthreads();
#pragma unroll
    for (int o = 1; o < 128; o <<= 1) {
        int v = (t >= o) ? sh[t - o] : 0;
        __syncthreads();
        sh[t] += v;
        __syncthreads();
    }
    g_boff[t] = sh[t] - c;
}
__global__ void __launch_bounds__(256) k_scan3() {
    int i = blockIdx.x * 256 + threadIdx.x;
    int off = g_off[i] + g_boff[i >> 8];
    g_off[i] = off;
    g_cur[i] = off;
    g_dinv[i] = rsqrtf((float)g_cnt[i] + 1.0f);
    if (i == 0) g_off[NN] = EE;
}
__global__ void k_fill(const void* __restrict__ ei) {
    int e = blockIdx.x * blockDim.x + threadIdx.x;
    if (e >= EE) return;
    int s = edge_src(ei, e);
    int d = edge_dst(ei, e);
    int slot = atomicAdd(&g_cur[d], 1);
    g_srcs[slot] = s;
}

// ---------------- pre-split: x -> g_q (split), weights -> g_wt transposed split ----------------
__global__ void __launch_bounds__(256) k_split(const float* __restrict__ x,
                                               const float* __restrict__ W1,
                                               const float* __restrict__ W2,
                                               const float* __restrict__ Wq,
                                               const float* __restrict__ Wk,
                                               const float* __restrict__ Wv) {
    int bx = blockIdx.x, tid = threadIdx.x;
    if (bx < 256) {
        // x rows [bx*128, bx*128+128) -> g_q_hi/lo
        size_t m0 = (size_t)bx * 128;
        const float4* X4 = (const float4*)(x + m0 * 128);
#pragma unroll
        for (int it = 0; it < 16; it++) {
            int idx = it * 256 + tid;
            int row = idx >> 5, c4 = idx & 31;
            float4 v = X4[idx];
            size_t o = (m0 + row) * 64 + c4 * 2;
            g_q_hi[o]     = pack_hi(v.x, v.y);
            g_q_hi[o + 1] = pack_hi(v.z, v.w);
            g_q_lo[o]     = pack_lo(v.x, v.y);
            g_q_lo[o + 1] = pack_lo(v.z, v.w);
        }
    } else {
        int w = bx - 256;  // 0..4
        const float* W = (w == 0) ? W1 : (w == 1) ? W2 : (w == 2) ? Wq : (w == 3) ? Wk : Wv;
        const float4* W4 = (const float4*)W;
        uint32_t* Hi = g_wt_hi + w * 8192;
        uint32_t* Lo = g_wt_lo + w * 8192;
        // item: (k-pair k2, n-quad n4): read W[2k2][n4*4..+3], W[2k2+1][...]
#pragma unroll
        for (int it = 0; it < 8; it++) {
            int item = it * 256 + tid;
            int k2 = item >> 5, n4 = item & 31;
            float4 va = W4[(2 * k2) * 32 + n4];
            float4 vb = W4[(2 * k2 + 1) * 32 + n4];
            float aa[4] = {va.x, va.y, va.z, va.w};
            float bb[4] = {vb.x, vb.y, vb.z, vb.w};
#pragma unroll
            for (int j = 0; j < 4; j++) {
                int n = n4 * 4 + j;
                Hi[n * 64 + k2] = pack_hi(aa[j], bb[j]);
                Lo[n * 64 + k2] = pack_lo(aa[j], bb[j]);
            }
        }
    }
}

// ---------------- GEMM core: ldmatrix + split-3 MMA over one 32-K chunk ----------------
__device__ __forceinline__ void mma_chunk(float d[4][4][4], uint32_t base,
                                          int wm, int wn, int lane) {
    uint32_t aHi = base, aLo = base + TILE_B;
    uint32_t bHi = base + 2 * TILE_B, bLo = base + 3 * TILE_B;
    uint32_t aOff = (uint32_t)((wm * 64 + (lane & 15)) * PADB + (lane >> 4) * 16);
    uint32_t bOff = (uint32_t)((wn * 32 + (lane & 7)) * PADB + ((lane >> 3) & 1) * 16);
#pragma unroll
    for (int ks = 0; ks < 2; ks++) {
        uint32_t bh[4][2], bl[4][2];
#pragma unroll
        for (int nt = 0; nt < 4; nt++) {
            LDSM2(bh[nt][0], bh[nt][1], bHi + bOff + nt * 8 * PADB + ks * 32);
            LDSM2(bl[nt][0], bl[nt][1], bLo + bOff + nt * 8 * PADB + ks * 32);
        }
#pragma unroll
        for (int mt = 0; mt < 4; mt++) {
            uint32_t ah0, ah1, ah2, ah3, al0, al1, al2, al3;
            LDSM4(ah0, ah1, ah2, ah3, aHi + aOff + mt * 16 * PADB + ks * 32);
            LDSM4(al0, al1, al2, al3, aLo + aOff + mt * 16 * PADB + ks * 32);
#pragma unroll
            for (int nt = 0; nt < 4; nt++) {
                MMA_BF16(d[mt][nt], ah0, ah1, ah2, ah3, bh[nt][0], bh[nt][1]);
                MMA_BF16(d[mt][nt], ah0, ah1, ah2, ah3, bl[nt][0], bl[nt][1]);
                MMA_BF16(d[mt][nt], al0, al1, al2, al3, bh[nt][0], bh[nt][1]);
            }
        }
    }
}

// load one 32-K chunk (4 tiles) via cp.async; global rows are 16 uint4 wide
__device__ __forceinline__ void load_chunk(uint32_t base,
                                           const uint4* Ah, const uint4* Al, size_t aRow0,
                                           const uint4* Bh, const uint4* Bl, size_t bRow0,
                                           int kc, int tid) {
#pragma unroll
    for (int it = 0; it < 2; it++) {
        int idx = it * 256 + tid;
        int row = idx >> 2, q = idx & 3;
        uint32_t doff = (uint32_t)(row * PADB + q * 16);
        size_t ga = (aRow0 + row) * 16 + kc * 4 + q;
        size_t gb = (bRow0 + row) * 16 + kc * 4 + q;
        cp16(base + doff,              Ah + ga);
        cp16(base + TILE_B + doff,     Al + ga);
        cp16(base + 2 * TILE_B + doff, Bh + gb);
        cp16(base + 3 * TILE_B + doff, Bl + gb);
    }
}

// epilogue: fp32 -> g_hs (dstMode 0), split-bf16 -> q (1) / k (2)
__device__ __forceinline__ void gemm_epilogue(float d[4][4][4], const float* bias,
                                              int dstMode, size_t m0,
                                              int wm, int wn, int gid, int tig) {
    float* C = (float*)g_hs;
    uint32_t* Hq = (dstMode == 1) ? g_q_hi : g_k_hi;
    uint32_t* Lq = (dstMode == 1) ? g_q_lo : g_k_lo;
#pragma unroll
    for (int mt = 0; mt < 4; mt++) {
        size_t row0 = m0 + wm * 64 + mt * 16 + gid;
        size_t row1 = row0 + 8;
#pragma unroll
        for (int nt = 0; nt < 4; nt++) {
            int col = wn * 32 + nt * 8 + tig * 2;
            float bx = 0.f, by = 0.f;
            if (bias) { bx = bias[col]; by = bias[col + 1]; }
            float v00 = d[mt][nt][0] + bx, v01 = d[mt][nt][1] + by;
            float v10 = d[mt][nt][2] + bx, v11 = d[mt][nt][3] + by;
            if (dstMode == 0) {
                *(float2*)(C + row0 * 128 + col) = make_float2(v00, v01);
                *(float2*)(C + row1 * 128 + col) = make_float2(v10, v11);
            } else {
                int ci = col >> 1;
                Hq[row0 * 64 + ci] = pack_hi(v00, v01);
                Lq[row0 * 64 + ci] = pack_lo(v00, v01);
                Hq[row1 * 64 + ci] = pack_hi(v10, v11);
                Lq[row1 * 64 + ci] = pack_lo(v10, v11);
            }
        }
    }
}

// ---------------- unified node GEMM: C[128-tile,128] = A @ W ----------------
// mode 0: conv1 (A = split x in g_q, W#0, dst g_hs)
// mode 1: conv2 (A = g_h, W#1, dst g_hs)
// mode 2: QKV   (A = g_h, W#(2+y), dst q/k/hs by blockIdx.y)
__global__ void __launch_bounds__(256, 2) k_tgemm(const float* __restrict__ bias0,
                                                  const float* __restrict__ bias1,
                                                  const float* __restrict__ bias2,
                                                  int mode) {
    extern __shared__ __align__(16) uint8_t dsm[];
    int tid = threadIdx.x, wid = tid >> 5, lane = tid & 31;
    int gid = lane >> 2, tig = lane & 3;
    int wm = wid >> 2, wn = wid & 3;
    size_t m0 = (size_t)blockIdx.x * 128;

    const uint32_t *srcHi, *srcLo;
    int widx, dstMode;
    const float* bias = nullptr;
    if (mode == 0)      { srcHi = g_q_hi; srcLo = g_q_lo; widx = 0; dstMode = 0; }
    else if (mode == 1) { srcHi = g_h_hi; srcLo = g_h_lo; widx = 1; dstMode = 0; }
    else {
        int y = blockIdx.y;
        srcHi = g_h_hi; srcLo = g_h_lo; widx = 2 + y;
        dstMode = (y == 0) ? 1 : (y == 1) ? 2 : 0;
        bias = (y == 0) ? bias0 : (y == 1) ? bias1 : bias2;
    }
    const uint4* Ah = (const uint4*)srcHi;
    const uint4* Al = (const uint4*)srcLo;
    const uint4* Bh = (const uint4*)(g_wt_hi + widx * 8192);
    const uint4* Bl = (const uint4*)(g_wt_lo + widx * 8192);
    uint32_t smBase = (uint32_t)__cvta_generic_to_shared(dsm);

    float d[4][4][4];
#pragma unroll
    for (int mt = 0; mt < 4; mt++)
#pragma unroll
        for (int nt = 0; nt < 4; nt++)
#pragma unroll
            for (int c = 0; c < 4; c++) d[mt][nt][c] = 0.f;

    load_chunk(smBase, Ah, Al, m0, Bh, Bl, 0, 0, tid);
    CP_COMMIT();
    for (int kc = 0; kc < 4; kc++) {
        if (kc < 3) {
            load_chunk(smBase + ((kc + 1) & 1) * STAGE_B, Ah, Al, m0, Bh, Bl, 0, kc + 1, tid);
            CP_COMMIT();
            CP_WAIT(1);
        } else {
            CP_WAIT(0);
        }
        __syncthreads();
        mma_chunk(d, smBase + (kc & 1) * STAGE_B, wm, wn, lane);
        __syncthreads();
    }
    gemm_epilogue(d, bias, dstMode, m0, wm, wn, gid, tig);
}

// ---------------- scores: S-tile = Q @ K^T * SCALE ----------------
#define SCALE 0.08838834764831845f

__global__ void __launch_bounds__(256, 2) k_tscores() {
    extern __shared__ __align__(16) uint8_t dsm[];
    int tid = threadIdx.x, wid = tid >> 5, lane = tid & 31;
    int gid = lane >> 2, tig = lane & 3;
    int wm = wid >> 2, wn = wid & 3;
    int g = blockIdx.z, ti = blockIdx.y, tj = blockIdx.x;

    size_t qrow = (size_t)(g * NG + ti * 128);
    size_t krow = (size_t)(g * NG + tj * 128);
    const uint4* Qh = (const uint4*)g_q_hi;
    const uint4* Ql = (const uint4*)g_q_lo;
    const uint4* Kh = (const uint4*)g_k_hi;
    const uint4* Kl = (const uint4*)g_k_lo;
    uint32_t smBase = (uint32_t)__cvta_generic_to_shared(dsm);

    float d[4][4][4];
#pragma unroll
    for (int mt = 0; mt < 4; mt++)
#pragma unroll
        for (int nt = 0; nt < 4; nt++)
#pragma unroll
            for (int c = 0; c < 4; c++) d[mt][nt][c] = 0.f;

    load_chunk(smBase, Qh, Ql, qrow, Kh, Kl, krow, 0, tid);
    CP_COMMIT();
    for (int kc = 0; kc < 4; kc++) {
        if (kc < 3) {
            load_chunk(smBase + ((kc + 1) & 1) * STAGE_B, Qh, Ql, qrow, Kh, Kl, krow, kc + 1, tid);
            CP_COMMIT();
            CP_WAIT(1);
        } else {
            CP_WAIT(0);
        }
        __syncthreads();
        mma_chunk(d, smBase + (kc & 1) * STAGE_B, wm, wn, lane);
        __syncthreads();
    }

    float* Sg = g_scores + (size_t)g * NG * NG;
#pragma unroll
    for (int mt = 0; mt < 4; mt++) {
        int i0 = ti * 128 + wm * 64 + mt * 16 + gid;
        int i1 = i0 + 8;
#pragma unroll
        for (int nt = 0; nt < 4; nt++) {
            int col = tj * 128 + wn * 32 + nt * 8 + tig * 2;
            *(float2*)(Sg + (size_t)i0 * NG + col) =
                make_float2(d[mt][nt][0] * SCALE, d[mt][nt][1] * SCALE);
            *(float2*)(Sg + (size_t)i1 * NG + col) =
                make_float2(d[mt][nt][2] * SCALE, d[mt][nt][3] * SCALE);
        }
    }
}

// ---------------- aggregate (writes h as split-bf16) ----------------
__global__ void __launch_bounds__(256) k_aggregate(const float* __restrict__ b) {
    int t = blockIdx.x * blockDim.x + threadIdx.x;
    int i = t >> 5;
    if (i >= NN) return;
    int lane = t & 31;

    float di = g_dinv[i];
    float4 self = g_hs[(size_t)i * 32 + lane];
    float4 acc;
    acc.x = di * self.x; acc.y = di * self.y;
    acc.z = di * self.z; acc.w = di * self.w;

    int j = g_off[i];
    int end = g_off[i + 1];
    for (; j + 1 < end; j += 2) {
        int s0 = g_srcs[j], s1 = g_srcs[j + 1];
        float w0 = g_dinv[s0], w1 = g_dinv[s1];
        float4 v0 = g_hs[(size_t)s0 * 32 + lane];
        float4 v1 = g_hs[(size_t)s1 * 32 + lane];
        acc.x += w0 * v0.x + w1 * v1.x;
        acc.y += w0 * v0.y + w1 * v1.y;
        acc.z += w0 * v0.z + w1 * v1.z;
        acc.w += w0 * v0.w + w1 * v1.w;
    }
    if (j < end) {
        int s0 = g_srcs[j];
        float w0 = g_dinv[s0];
        float4 v0 = g_hs[(size_t)s0 * 32 + lane];
        acc.x += w0 * v0.x; acc.y += w0 * v0.y;
        acc.z += w0 * v0.z; acc.w += w0 * v0.w;
    }
    float4 bb = ((const float4*)b)[lane];
    float o0 = fmaxf(acc.x * di + bb.x, 0.f);
    float o1 = fmaxf(acc.y * di + bb.y, 0.f);
    float o2 = fmaxf(acc.z * di + bb.z, 0.f);
    float o3 = fmaxf(acc.w * di + bb.w, 0.f);
    size_t base = (size_t)i * 64 + lane * 2;
    g_h_hi[base]     = pack_hi(o0, o1);
    g_h_hi[base + 1] = pack_hi(o2, o3);
    g_h_lo[base]     = pack_lo(o0, o1);
    g_h_lo[base + 1] = pack_lo(o2, o3);
}

// ---------------- per-row softmax stats ----------------
__global__ void k_rowstats() {
    int gt = blockIdx.x * blockDim.x + threadIdx.x;
    int row = gt >> 5, lane = gt & 31;
    if (row >= GG * NG) return;
    const float* r = g_scores + (size_t)row * NG;
    float v[16];
    float m = -1e30f;
#pragma unroll
    for (int i = 0; i < 16; i++) { v[i] = r[lane + i * 32]; m = fmaxf(m, v[i]); }
#pragma unroll
    for (int o = 16; o > 0; o >>= 1) m = fmaxf(m, __shfl_xor_sync(0xffffffffu, m, o));
    float z = 0.f;
#pragma unroll
    for (int i = 0; i < 16; i++) z += __expf(v[i] - m);
#pragma unroll
    for (int o = 16; o > 0; o >>= 1) z += __shfl_xor_sync(0xffffffffu, z, o);
    if (lane == 0) { g_rowm[row] = m; g_rowz[row] = 1.0f / z; g_w[row] = 0.f; }
}

// ---------------- column weights ----------------
__global__ void __launch_bounds__(512) k_colsum() {
    __shared__ float sm_m[128];
    __shared__ float sm_zi[128];
    int g = blockIdx.x, it = blockIdx.y, j = threadIdx.x;
    if (j < 128) {
        sm_m[j]  = g_rowm[g * NG + it * 128 + j];
        sm_zi[j] = g_rowz[g * NG + it * 128 + j];
    }
    __syncthreads();
    const float* Sg = g_scores + (size_t)g * NG * NG + (size_t)it * 128 * NG;
    float w = 0.f;
#pragma unroll 4
    for (int i = 0; i < 128; i++)
        w += __expf(Sg[(size_t)i * NG + j] - sm_m[i]) * sm_zi[i];
    atomicAdd(&g_w[g * NG + j], w);
}

// ---------------- pooled + MLP head ----------------
__global__ void __launch_bounds__(128) k_pooled_head(const float* __restrict__ Wh1,
                                                     const float* __restrict__ bh1,
                                                     const float* __restrict__ Wh2,
                                                     const float* __restrict__ bh2,
                                                     float* __restrict__ out) {
    int g = blockIdx.x, d = threadIdx.x;
    __shared__ float ws[NG];
    __shared__ float pooled[HH];
    __shared__ float hid[64];
    for (int i = d; i < NG; i += 128) ws[i] = g_w[g * NG + i];
    __syncthreads();
    const float* vg = (const float*)g_hs + (size_t)g * NG * HH;
    float acc = 0.f;
    for (int j = 0; j < NG; j++) acc += ws[j] * vg[j * HH + d];
    pooled[d] = acc * (1.0f / (float)NG);
    __syncthreads();
    if (d < 64) {
        float h = bh1[d];
#pragma unroll 8
        for (int k = 0; k < HH; k++) h += pooled[k] * Wh1[k * 64 + d];
        hid[d] = fmaxf(h, 0.f);
    }
    __syncthreads();
    if (d == 0) {
        float o = bh2[0];
#pragma unroll 8
        for (int h = 0; h < 64; h++) o += hid[h] * Wh2[h];
        out[g] = o;
    }
}

// ---------------- launch ----------------
extern "C" void kernel_launch(void* const* d_in, const int* in_sizes, int n_in,
                              void* d_out, int out_size) {
    const float* x   = (const float*)d_in[0];
    const void*  ei  = d_in[1];
    const float* W1  = (const float*)d_in[3];
    const float* b1  = (const float*)d_in[4];
    const float* W2  = (const float*)d_in[5];
    const float* b2  = (const float*)d_in[6];
    const float* Wq  = (const float*)d_in[7];
    const float* bq  = (const float*)d_in[8];
    const float* Wk  = (const float*)d_in[9];
    const float* bk  = (const float*)d_in[10];
    const float* Wv  = (const float*)d_in[11];
    const float* bv  = (const float*)d_in[12];
    const float* Wh1 = (const float*)d_in[13];
    const float* bh1 = (const float*)d_in[14];
    const float* Wh2 = (const float*)d_in[15];
    const float* bh2 = (const float*)d_in[16];
    float* out = (float*)d_out;

    cudaFuncSetAttribute(k_tgemm,   cudaFuncAttributeMaxDynamicSharedMemorySize, DSMEM);
    cudaFuncSetAttribute(k_tscores, cudaFuncAttributeMaxDynamicSharedMemorySize, DSMEM);

    k_dtype_zero<<<NN / 256, 256>>>(ei);                     // #1
    k_hist<<<EE / 256, 256>>>(ei);                           // #2
    k_split<<<261, 256>>>(x, W1, W2, Wq, Wk, Wv);            // #3
    k_tgemm<<<NN / 128, 256, DSMEM>>>(nullptr, nullptr, nullptr, 0);  // #4 conv1 (profiled)
    k_scan1<<<NN / 256, 256>>>();                            // #5
    k_scan2<<<1, 128>>>();                                   // #6
    k_scan3<<<NN / 256, 256>>>();                            // #7
    k_fill<<<EE / 256, 256>>>(ei);                           // #8

    k_aggregate<<<NN * 32 / 256, 256>>>(b1);
    k_tgemm<<<NN / 128, 256, DSMEM>>>(nullptr, nullptr, nullptr, 1);  // conv2
    k_aggregate<<<NN * 32 / 256, 256>>>(b2);

    dim3 qkv(NN / 128, 3);
    k_tgemm<<<qkv, 256, DSMEM>>>(bq, bk, bv, 2);             // fused QKV

    dim3 sg(NG / 128, NG / 128, GG);
    k_tscores<<<sg, 256, DSMEM>>>();
    k_rowstats<<<GG * NG * 32 / 256, 256>>>();
    dim3 cs(GG, NG / 128);
    k_colsum<<<cs, 512>>>();
    k_pooled_head<<<GG, HH>>>(Wh1, bh1, Wh2, bh2, out);
}

// round 11
// speedup vs baseline: 1.5009x; 1.0299x over previous
#include <cuda_runtime.h>
#include <cuda_bf16.h>
#include <cstdint>
#include <cstddef>

#define NN 32768
#define EE 524288
#define HH 128
#define GG 64
#define NG 512   // nodes per graph

// ---------------- device scratch (static, no allocations) ----------------
__device__ int      g_ei64;
__device__ int      g_cnt[NN];
__device__ int      g_off[NN + 1];
__device__ int      g_cur[NN];
__device__ int      g_bsum[128];
__device__ int      g_boff[128];
__device__ int      g_srcs[EE];
__device__ float    g_dinv[NN];
__device__ float4   g_hs[NN * 32];                 // fp32 messages; later reused for V
__device__ uint32_t g_h_hi[NN * 64];               // h split-bf16 (2 elems per uint32)
__device__ uint32_t g_h_lo[NN * 64];
__device__ uint32_t g_q_hi[NN * 64];               // also holds split x before QKV
__device__ uint32_t g_q_lo[NN * 64];
__device__ uint32_t g_k_hi[NN * 64];
__device__ uint32_t g_k_lo[NN * 64];
__device__ uint32_t g_wt_hi[5 * 128 * 64];         // 5 weights, transposed [n][k] split-bf16
__device__ uint32_t g_wt_lo[5 * 128 * 64];
__device__ float    g_scores[(size_t)GG * NG * NG]; // 64 MB scaled scores
__device__ float    g_rowm[GG * NG];
__device__ float    g_rowz[GG * NG];
__device__ float    g_w[GG * NG];

// ---------------- mma.sync / ldmatrix / cp.async helpers ----------------
#define MMA_BF16(D, a0, a1, a2, a3, b0, b1)                                   \
    asm volatile(                                                             \
        "mma.sync.aligned.m16n8k16.row.col.f32.bf16.bf16.f32 "                \
        "{%0,%1,%2,%3}, {%4,%5,%6,%7}, {%8,%9}, {%0,%1,%2,%3};"               \
        : "+f"((D)[0]), "+f"((D)[1]), "+f"((D)[2]), "+f"((D)[3])              \
        : "r"(a0), "r"(a1), "r"(a2), "r"(a3), "r"(b0), "r"(b1))

#define LDSM4(r0, r1, r2, r3, addr)                                           \
    asm volatile("ldmatrix.sync.aligned.m8n8.x4.shared.b16 {%0,%1,%2,%3}, [%4];" \
                 : "=r"(r0), "=r"(r1), "=r"(r2), "=r"(r3) : "r"(addr))

#define LDSM2(r0, r1, addr)                                                   \
    asm volatile("ldmatrix.sync.aligned.m8n8.x2.shared.b16 {%0,%1}, [%2];"    \
                 : "=r"(r0), "=r"(r1) : "r"(addr))

__device__ __forceinline__ void cp16(uint32_t dst, const void* src) {
    asm volatile("cp.async.cg.shared.global [%0], [%1], 16;" :: "r"(dst), "l"(src));
}
#define CP_COMMIT() asm volatile("cp.async.commit_group;" ::: "memory")
#define CP_WAIT(n)  asm volatile("cp.async.wait_group %0;" :: "n"(n) : "memory")

#define PADB 80            // 32 bf16 per row padded to 80 B (bank-disjoint ldmatrix)
#define TILE_B (128 * PADB)     // 10240 B per tile
#define STAGE_B (4 * TILE_B)    // 40960 B per pipeline stage
#define DSMEM (2 * STAGE_B)     // 81920 B dynamic smem

__device__ __forceinline__ uint32_t pack_hi(float a, float b) {
    __nv_bfloat162 h = __halves2bfloat162(__float2bfloat16(a), __float2bfloat16(b));
    return *(uint32_t*)&h;
}
__device__ __forceinline__ uint32_t pack_lo(float a, float b) {
    __nv_bfloat16 ha = __float2bfloat16(a), hb = __float2bfloat16(b);
    __nv_bfloat162 l = __floats2bfloat162_rn(a - __bfloat162float(ha),
                                             b - __bfloat162float(hb));
    return *(uint32_t*)&l;
}

// ---------------- edge index accessors ----------------
__device__ __forceinline__ int edge_src(const void* ei, int e) {
    int v = g_ei64 ? (int)((const long long*)ei)[e] : ((const int*)ei)[e];
    return v & (NN - 1);
}
__device__ __forceinline__ int edge_dst(const void* ei, int e) {
    int v = g_ei64 ? (int)((const long long*)ei)[EE + e] : ((const int*)ei)[EE + e];
    return v & (NN - 1);
}

__global__ void __launch_bounds__(256) k_dtype_zero(const void* ei) {
    int i = blockIdx.x * 256 + threadIdx.x;
    g_cnt[i] = 0;
    if (blockIdx.x == 0) {
        __shared__ int s_ok;
        if (threadIdx.x == 0) s_ok = 1;
        __syncthreads();
        const long long* p = (const long long*)ei;
        int bad = 0;
#pragma unroll
        for (int k = 0; k < 4; k++) {
            long long v = p[threadIdx.x * 4 + k];
            if (v < 0 || v >= NN) bad = 1;
        }
        if (bad) atomicExch(&s_ok, 0);
        __syncthreads();
        if (threadIdx.x == 0) g_ei64 = s_ok;
    }
}

__global__ void k_hist(const void* __restrict__ ei) {
    int e = blockIdx.x * blockDim.x + threadIdx.x;
    if (e < EE) atomicAdd(&g_cnt[edge_dst(ei, e)], 1);
}
__global__ void __launch_bounds__(256) k_scan1() {
    __shared__ int sh[256];
    int t = threadIdx.x;
    int i = blockIdx.x * 256 + t;
    int c = g_cnt[i];
    sh[t] = c;
    __syncthreads();
#pragma unroll
    for (int o = 1; o < 256; o <<= 1) {
        int v = (t >= o) ? sh[t - o] : 0;
        __syncthreads();
        sh[t] += v;
        __syncthreads();
    }
    g_off[i] = sh[t] - c;
    if (t == 255) g_bsum[blockIdx.x] = sh[255];
}
__global__ void __launch_bounds__(128) k_scan2() {
    __shared__ int sh[128];
    int t = threadIdx.x;
    int c = g_bsum[t];
    sh[t] = c;
    __syncthreads();
#pragma unroll
    for (int o = 1; o < 128; o <<= 1) {
        int v = (t >= o) ? sh[t - o] : 0;
        __syncthreads();
        sh[t] += v;
        __syncthreads();
    }
    g_boff[t] = sh[t] - c;
}
__global__ void __launch_bounds__(256) k_scan3() {
    int i = blockIdx.x * 256 + threadIdx.x;
    int off = g_off[i] + g_boff[i >> 8];
    g_off[i] = off;
    g_cur[i] = off;
    g_dinv[i] = rsqrtf((float)g_cnt[i] + 1.0f);
    if (i == 0) g_off[NN] = EE;
}
__global__ void k_fill(const void* __restrict__ ei) {
    int e = blockIdx.x * blockDim.x + threadIdx.x;
    if (e >= EE) return;
    int s = edge_src(ei, e);
    int d = edge_dst(ei, e);
    int slot = atomicAdd(&g_cur[d], 1);
    g_srcs[slot] = s;
}

// ---------------- pre-split: x -> g_q (split), weights -> g_wt transposed split ----------------
__global__ void __launch_bounds__(256) k_split(const float* __restrict__ x,
                                               const float* __restrict__ W1,
                                               const float* __restrict__ W2,
                                               const float* __restrict__ Wq,
                                               const float* __restrict__ Wk,
                                               const float* __restrict__ Wv) {
    int bx = blockIdx.x, tid = threadIdx.x;
    if (bx < 256) {
        size_t m0 = (size_t)bx * 128;
        const float4* X4 = (const float4*)(x + m0 * 128);
#pragma unroll
        for (int it = 0; it < 16; it++) {
            int idx = it * 256 + tid;
            int row = idx >> 5, c4 = idx & 31;
            float4 v = X4[idx];
            size_t o = (m0 + row) * 64 + c4 * 2;
            g_q_hi[o]     = pack_hi(v.x, v.y);
            g_q_hi[o + 1] = pack_hi(v.z, v.w);
            g_q_lo[o]     = pack_lo(v.x, v.y);
            g_q_lo[o + 1] = pack_lo(v.z, v.w);
        }
    } else {
        int w = bx - 256;  // 0..4
        const float* W = (w == 0) ? W1 : (w == 1) ? W2 : (w == 2) ? Wq : (w == 3) ? Wk : Wv;
        const float4* W4 = (const float4*)W;
        uint32_t* Hi = g_wt_hi + w * 8192;
        uint32_t* Lo = g_wt_lo + w * 8192;
#pragma unroll
        for (int it = 0; it < 8; it++) {
            int item = it * 256 + tid;
            int k2 = item >> 5, n4 = item & 31;
            float4 va = W4[(2 * k2) * 32 + n4];
            float4 vb = W4[(2 * k2 + 1) * 32 + n4];
            float aa[4] = {va.x, va.y, va.z, va.w};
            float bb[4] = {vb.x, vb.y, vb.z, vb.w};
#pragma unroll
            for (int j = 0; j < 4; j++) {
                int n = n4 * 4 + j;
                Hi[n * 64 + k2] = pack_hi(aa[j], bb[j]);
                Lo[n * 64 + k2] = pack_lo(aa[j], bb[j]);
            }
        }
    }
}

// ---------------- GEMM core: ldmatrix + split-3 MMA over one 32-K chunk ----------------
__device__ __forceinline__ void mma_chunk(float d[4][4][4], uint32_t base,
                                          int wm, int wn, int lane) {
    uint32_t aHi = base, aLo = base + TILE_B;
    uint32_t bHi = base + 2 * TILE_B, bLo = base + 3 * TILE_B;
    uint32_t aOff = (uint32_t)((wm * 64 + (lane & 15)) * PADB + (lane >> 4) * 16);
    uint32_t bOff = (uint32_t)((wn * 32 + (lane & 7)) * PADB + ((lane >> 3) & 1) * 16);
#pragma unroll
    for (int ks = 0; ks < 2; ks++) {
        uint32_t bh[4][2], bl[4][2];
#pragma unroll
        for (int nt = 0; nt < 4; nt++) {
            LDSM2(bh[nt][0], bh[nt][1], bHi + bOff + nt * 8 * PADB + ks * 32);
            LDSM2(bl[nt][0], bl[nt][1], bLo + bOff + nt * 8 * PADB + ks * 32);
        }
#pragma unroll
        for (int mt = 0; mt < 4; mt++) {
            uint32_t ah0, ah1, ah2, ah3, al0, al1, al2, al3;
            LDSM4(ah0, ah1, ah2, ah3, aHi + aOff + mt * 16 * PADB + ks * 32);
            LDSM4(al0, al1, al2, al3, aLo + aOff + mt * 16 * PADB + ks * 32);
#pragma unroll
            for (int nt = 0; nt < 4; nt++) {
                MMA_BF16(d[mt][nt], ah0, ah1, ah2, ah3, bh[nt][0], bh[nt][1]);
                MMA_BF16(d[mt][nt], ah0, ah1, ah2, ah3, bl[nt][0], bl[nt][1]);
                MMA_BF16(d[mt][nt], al0, al1, al2, al3, bh[nt][0], bh[nt][1]);
            }
        }
    }
}

// load one 32-K chunk (4 tiles) via cp.async; global rows are 16 uint4 wide
__device__ __forceinline__ void load_chunk(uint32_t base,
                                           const uint4* Ah, const uint4* Al, size_t aRow0,
                                           const uint4* Bh, const uint4* Bl, size_t bRow0,
                                           int kc, int tid) {
#pragma unroll
    for (int it = 0; it < 2; it++) {
        int idx = it * 256 + tid;
        int row = idx >> 2, q = idx & 3;
        uint32_t doff = (uint32_t)(row * PADB + q * 16);
        size_t ga = (aRow0 + row) * 16 + kc * 4 + q;
        size_t gb = (bRow0 + row) * 16 + kc * 4 + q;
        cp16(base + doff,              Ah + ga);
        cp16(base + TILE_B + doff,     Al + ga);
        cp16(base + 2 * TILE_B + doff, Bh + gb);
        cp16(base + 3 * TILE_B + doff, Bl + gb);
    }
}

// epilogue: fp32 -> g_hs (dstMode 0), split-bf16 -> q (1) / k (2)
__device__ __forceinline__ void gemm_epilogue(float d[4][4][4], const float* bias,
                                              int dstMode, size_t m0,
                                              int wm, int wn, int gid, int tig) {
    float* C = (float*)g_hs;
    uint32_t* Hq = (dstMode == 1) ? g_q_hi : g_k_hi;
    uint32_t* Lq = (dstMode == 1) ? g_q_lo : g_k_lo;
#pragma unroll
    for (int mt = 0; mt < 4; mt++) {
        size_t row0 = m0 + wm * 64 + mt * 16 + gid;
        size_t row1 = row0 + 8;
#pragma unroll
        for (int nt = 0; nt < 4; nt++) {
            int col = wn * 32 + nt * 8 + tig * 2;
            float bx = 0.f, by = 0.f;
            if (bias) { bx = bias[col]; by = bias[col + 1]; }
            float v00 = d[mt][nt][0] + bx, v01 = d[mt][nt][1] + by;
            float v10 = d[mt][nt][2] + bx, v11 = d[mt][nt][3] + by;
            if (dstMode == 0) {
                *(float2*)(C + row0 * 128 + col) = make_float2(v00, v01);
                *(float2*)(C + row1 * 128 + col) = make_float2(v10, v11);
            } else {
                int ci = col >> 1;
                Hq[row0 * 64 + ci] = pack_hi(v00, v01);
                Lq[row0 * 64 + ci] = pack_lo(v00, v01);
                Hq[row1 * 64 + ci] = pack_hi(v10, v11);
                Lq[row1 * 64 + ci] = pack_lo(v10, v11);
            }
        }
    }
}

// ---------------- unified node GEMM: C[128-tile,128] = A @ W ----------------
// mode 0: conv1 (A = split x in g_q, W#0, dst g_hs)
// mode 1: conv2 (A = g_h, W#1, dst g_hs)
// mode 2: QKV   (A = g_h, W#(2+y), dst q/k/hs by blockIdx.y)
__global__ void __launch_bounds__(256, 2) k_tgemm(const float* __restrict__ bias0,
                                                  const float* __restrict__ bias1,
                                                  const float* __restrict__ bias2,
                                                  int mode) {
    extern __shared__ __align__(16) uint8_t dsm[];
    int tid = threadIdx.x, wid = tid >> 5, lane = tid & 31;
    int gid = lane >> 2, tig = lane & 3;
    int wm = wid >> 2, wn = wid & 3;
    size_t m0 = (size_t)blockIdx.x * 128;

    const uint32_t *srcHi, *srcLo;
    int widx, dstMode;
    const float* bias = nullptr;
    if (mode == 0)      { srcHi = g_q_hi; srcLo = g_q_lo; widx = 0; dstMode = 0; }
    else if (mode == 1) { srcHi = g_h_hi; srcLo = g_h_lo; widx = 1; dstMode = 0; }
    else {
        int y = blockIdx.y;
        srcHi = g_h_hi; srcLo = g_h_lo; widx = 2 + y;
        dstMode = (y == 0) ? 1 : (y == 1) ? 2 : 0;
        bias = (y == 0) ? bias0 : (y == 1) ? bias1 : bias2;
    }
    const uint4* Ah = (const uint4*)srcHi;
    const uint4* Al = (const uint4*)srcLo;
    const uint4* Bh = (const uint4*)(g_wt_hi + widx * 8192);
    const uint4* Bl = (const uint4*)(g_wt_lo + widx * 8192);
    uint32_t smBase = (uint32_t)__cvta_generic_to_shared(dsm);

    float d[4][4][4];
#pragma unroll
    for (int mt = 0; mt < 4; mt++)
#pragma unroll
        for (int nt = 0; nt < 4; nt++)
#pragma unroll
            for (int c = 0; c < 4; c++) d[mt][nt][c] = 0.f;

    load_chunk(smBase, Ah, Al, m0, Bh, Bl, 0, 0, tid);
    CP_COMMIT();
#pragma unroll
    for (int kc = 0; kc < 4; kc++) {
        CP_WAIT(0);
        __syncthreads();   // chunk kc visible + stage (kc+1)&1 drained by all warps
        if (kc < 3) {
            load_chunk(smBase + ((kc + 1) & 1) * STAGE_B, Ah, Al, m0, Bh, Bl, 0, kc + 1, tid);
            CP_COMMIT();
        }
        mma_chunk(d, smBase + (kc & 1) * STAGE_B, wm, wn, lane);
    }
    gemm_epilogue(d, bias, dstMode, m0, wm, wn, gid, tig);
}

// ---------------- scores: S-tile = Q @ K^T * SCALE ----------------
#define SCALE 0.08838834764831845f

__global__ void __launch_bounds__(256, 2) k_tscores() {
    extern __shared__ __align__(16) uint8_t dsm[];
    int tid = threadIdx.x, wid = tid >> 5, lane = tid & 31;
    int gid = lane >> 2, tig = lane & 3;
    int wm = wid >> 2, wn = wid & 3;
    int g = blockIdx.z, ti = blockIdx.y, tj = blockIdx.x;

    size_t qrow = (size_t)(g * NG + ti * 128);
    size_t krow = (size_t)(g * NG + tj * 128);
    const uint4* Qh = (const uint4*)g_q_hi;
    const uint4* Ql = (const uint4*)g_q_lo;
    const uint4* Kh = (const uint4*)g_k_hi;
    const uint4* Kl = (const uint4*)g_k_lo;
    uint32_t smBase = (uint32_t)__cvta_generic_to_shared(dsm);

    float d[4][4][4];
#pragma unroll
    for (int mt = 0; mt < 4; mt++)
#pragma unroll
        for (int nt = 0; nt < 4; nt++)
#pragma unroll
            for (int c = 0; c < 4; c++) d[mt][nt][c] = 0.f;

    load_chunk(smBase, Qh, Ql, qrow, Kh, Kl, krow, 0, tid);
    CP_COMMIT();
#pragma unroll
    for (int kc = 0; kc < 4; kc++) {
        CP_WAIT(0);
        __syncthreads();
        if (kc < 3) {
            load_chunk(smBase + ((kc + 1) & 1) * STAGE_B, Qh, Ql, qrow, Kh, Kl, krow, kc + 1, tid);
            CP_COMMIT();
        }
        mma_chunk(d, smBase + (kc & 1) * STAGE_B, wm, wn, lane);
    }

    float* Sg = g_scores + (size_t)g * NG * NG;
#pragma unroll
    for (int mt = 0; mt < 4; mt++) {
        int i0 = ti * 128 + wm * 64 + mt * 16 + gid;
        int i1 = i0 + 8;
#pragma unroll
        for (int nt = 0; nt < 4; nt++) {
            int col = tj * 128 + wn * 32 + nt * 8 + tig * 2;
            *(float2*)(Sg + (size_t)i0 * NG + col) =
                make_float2(d[mt][nt][0] * SCALE, d[mt][nt][1] * SCALE);
            *(float2*)(Sg + (size_t)i1 * NG + col) =
                make_float2(d[mt][nt][2] * SCALE, d[mt][nt][3] * SCALE);
        }
    }
}

// ---------------- aggregate (writes h as split-bf16); 4-wide MLP gather ----------------
__global__ void __launch_bounds__(256) k_aggregate(const float* __restrict__ b) {
    int t = blockIdx.x * blockDim.x + threadIdx.x;
    int i = t >> 5;
    if (i >= NN) return;
    int lane = t & 31;

    float di = g_dinv[i];
    float4 self = g_hs[(size_t)i * 32 + lane];
    float4 acc;
    acc.x = di * self.x; acc.y = di * self.y;
    acc.z = di * self.z; acc.w = di * self.w;

    int j = g_off[i];
    int end = g_off[i + 1];
    for (; j + 3 < end; j += 4) {
        int s0 = g_srcs[j], s1 = g_srcs[j + 1], s2 = g_srcs[j + 2], s3 = g_srcs[j + 3];
        float w0 = g_dinv[s0], w1 = g_dinv[s1], w2 = g_dinv[s2], w3 = g_dinv[s3];
        float4 v0 = g_hs[(size_t)s0 * 32 + lane];
        float4 v1 = g_hs[(size_t)s1 * 32 + lane];
        float4 v2 = g_hs[(size_t)s2 * 32 + lane];
        float4 v3 = g_hs[(size_t)s3 * 32 + lane];
        acc.x += w0 * v0.x + w1 * v1.x + w2 * v2.x + w3 * v3.x;
        acc.y += w0 * v0.y + w1 * v1.y + w2 * v2.y + w3 * v3.y;
        acc.z += w0 * v0.z + w1 * v1.z + w2 * v2.z + w3 * v3.z;
        acc.w += w0 * v0.w + w1 * v1.w + w2 * v2.w + w3 * v3.w;
    }
    for (; j < end; j++) {
        int s0 = g_srcs[j];
        float w0 = g_dinv[s0];
        float4 v0 = g_hs[(size_t)s0 * 32 + lane];
        acc.x += w0 * v0.x; acc.y += w0 * v0.y;
        acc.z += w0 * v0.z; acc.w += w0 * v0.w;
    }
    float4 bb = ((const float4*)b)[lane];
    float o0 = fmaxf(acc.x * di + bb.x, 0.f);
    float o1 = fmaxf(acc.y * di + bb.y, 0.f);
    float o2 = fmaxf(acc.z * di + bb.z, 0.f);
    float o3 = fmaxf(acc.w * di + bb.w, 0.f);
    size_t base = (size_t)i * 64 + lane * 2;
    g_h_hi[base]     = pack_hi(o0, o1);
    g_h_hi[base + 1] = pack_hi(o2, o3);
    g_h_lo[base]     = pack_lo(o0, o1);
    g_h_lo[base + 1] = pack_lo(o2, o3);
}

// ---------------- per-row softmax stats ----------------
__global__ void k_rowstats() {
    int gt = blockIdx.x * blockDim.x + threadIdx.x;
    int row = gt >> 5, lane = gt & 31;
    if (row >= GG * NG) return;
    const float* r = g_scores + (size_t)row * NG;
    float v[16];
    float m = -1e30f;
#pragma unroll
    for (int i = 0; i < 16; i++) { v[i] = r[lane + i * 32]; m = fmaxf(m, v[i]); }
#pragma unroll
    for (int o = 16; o > 0; o >>= 1) m = fmaxf(m, __shfl_xor_sync(0xffffffffu, m, o));
    float z = 0.f;
#pragma unroll
    for (int i = 0; i < 16; i++) z += __expf(v[i] - m);
#pragma unroll
    for (int o = 16; o > 0; o >>= 1) z += __shfl_xor_sync(0xffffffffu, z, o);
    if (lane == 0) { g_rowm[row] = m; g_rowz[row] = 1.0f / z; g_w[row] = 0.f; }
}

// ---------------- column weights ----------------
__global__ void __launch_bounds__(512) k_colsum() {
    __shared__ float sm_m[128];
    __shared__ float sm_zi[128];
    int g = blockIdx.x, it = blockIdx.y, j = threadIdx.x;
    if (j < 128) {
        sm_m[j]  = g_rowm[g * NG + it * 128 + j];
        sm_zi[j] = g_rowz[g * NG + it * 128 + j];
    }
    __syncthreads();
    const float* Sg = g_scores + (size_t)g * NG * NG + (size_t)it * 128 * NG;
    float w = 0.f;
#pragma unroll 4
    for (int i = 0; i < 128; i++)
        w += __expf(Sg[(size_t)i * NG + j] - sm_m[i]) * sm_zi[i];
    atomicAdd(&g_w[g * NG + j], w);
}

// ---------------- pooled + MLP head ----------------
__global__ void __launch_bounds__(128) k_pooled_head(const float* __restrict__ Wh1,
                                                     const float* __restrict__ bh1,
                                                     const float* __restrict__ Wh2,
                                                     const float* __restrict__ bh2,
                                                     float* __restrict__ out) {
    int g = blockIdx.x, d = threadIdx.x;
    __shared__ float ws[NG];
    __shared__ float pooled[HH];
    __shared__ float hid[64];
    for (int i = d; i < NG; i += 128) ws[i] = g_w[g * NG + i];
    __syncthreads();
    const float* vg = (const float*)g_hs + (size_t)g * NG * HH;
    float acc = 0.f;
    for (int j = 0; j < NG; j++) acc += ws[j] * vg[j * HH + d];
    pooled[d] = acc * (1.0f / (float)NG);
    __syncthreads();
    if (d < 64) {
        float h = bh1[d];
#pragma unroll 8
        for (int k = 0; k < HH; k++) h += pooled[k] * Wh1[k * 64 + d];
        hid[d] = fmaxf(h, 0.f);
    }
    __syncthreads();
    if (d == 0) {
        float o = bh2[0];
#pragma unroll 8
        for (int h = 0; h < 64; h++) o += hid[h] * Wh2[h];
        out[g] = o;
    }
}

// ---------------- launch ----------------
extern "C" void kernel_launch(void* const* d_in, const int* in_sizes, int n_in,
                              void* d_out, int out_size) {
    const float* x   = (const float*)d_in[0];
    const void*  ei  = d_in[1];
    const float* W1  = (const float*)d_in[3];
    const float* b1  = (const float*)d_in[4];
    const float* W2  = (const float*)d_in[5];
    const float* b2  = (const float*)d_in[6];
    const float* Wq  = (const float*)d_in[7];
    const float* bq  = (const float*)d_in[8];
    const float* Wk  = (const float*)d_in[9];
    const float* bk  = (const float*)d_in[10];
    const float* Wv  = (const float*)d_in[11];
    const float* bv  = (const float*)d_in[12];
    const float* Wh1 = (const float*)d_in[13];
    const float* bh1 = (const float*)d_in[14];
    const float* Wh2 = (const float*)d_in[15];
    const float* bh2 = (const float*)d_in[16];
    float* out = (float*)d_out;

    cudaFuncSetAttribute(k_tgemm,   cudaFuncAttributeMaxDynamicSharedMemorySize, DSMEM);
    cudaFuncSetAttribute(k_tscores, cudaFuncAttributeMaxDynamicSharedMemorySize, DSMEM);

    k_dtype_zero<<<NN / 256, 256>>>(ei);                     // #1
    k_hist<<<EE / 256, 256>>>(ei);                           // #2
    k_split<<<261, 256>>>(x, W1, W2, Wq, Wk, Wv);            // #3
    k_tgemm<<<NN / 128, 256, DSMEM>>>(nullptr, nullptr, nullptr, 0);  // #4 conv1 (profiled)
    k_scan1<<<NN / 256, 256>>>();                            // #5
    k_scan2<<<1, 128>>>();                                   // #6
    k_scan3<<<NN / 256, 256>>>();                            // #7
    k_fill<<<EE / 256, 256>>>(ei);                           // #8

    k_aggregate<<<NN * 32 / 256, 256>>>(b1);
    k_tgemm<<<NN / 128, 256, DSMEM>>>(nullptr, nullptr, nullptr, 1);  // conv2
    k_aggregate<<<NN * 32 / 256, 256>>>(b2);

    dim3 qkv(NN / 128, 3);
    k_tgemm<<<qkv, 256, DSMEM>>>(bq, bk, bv, 2);             // fused QKV

    dim3 sg(NG / 128, NG / 128, GG);
    k_tscores<<<sg, 256, DSMEM>>>();
    k_rowstats<<<GG * NG * 32 / 256, 256>>>();
    dim3 cs(GG, NG / 128);
    k_colsum<<<cs, 512>>>();
    k_pooled_head<<<GG, HH>>>(Wh1, bh1, Wh2, bh2, out);
}